// round 8
// baseline (speedup 1.0000x reference)
#include <cuda_runtime.h>
#include <cstdint>

#define H_ 128
#define W_ 128
#define HW 16384
#define CIN 384
#define CQ 384
#define C3 1152
#define NH 6
#define HD 64
#define NB 4
#define KDIM 384          // K for both GEMMs
#define NSLAB 12          // 384 / 32

// Scratch (no allocation allowed).
__device__ float g_xT   [(size_t)NB * HW * CIN];  // x transposed  [b][hw][c]
__device__ float g_qkv  [(size_t)NB * C3 * HW];   // qkv           [b][c3][hw]
__device__ float g_attnT[(size_t)NB * HW * CQ];   // attn sum      [b][hw][c]

// ===========================================================================
// mma.sync helpers (baseline PTX, valid for every sm_103 gencode pass)
// ===========================================================================
static __device__ __forceinline__ void mma_bf16(
    float* d, const uint32_t* a, const uint32_t* b)
{
    asm volatile(
        "mma.sync.aligned.m16n8k16.row.col.f32.bf16.bf16.f32 "
        "{%0,%1,%2,%3}, {%4,%5,%6,%7}, {%8,%9}, {%0,%1,%2,%3};"
        : "+f"(d[0]), "+f"(d[1]), "+f"(d[2]), "+f"(d[3])
        : "r"(a[0]), "r"(a[1]), "r"(a[2]), "r"(a[3]),
          "r"(b[0]), "r"(b[1]));
}

static __device__ __forceinline__ void ldm4(uint32_t* r, uint32_t addr)
{
    asm volatile(
        "ldmatrix.sync.aligned.m8n8.x4.shared.b16 {%0,%1,%2,%3}, [%4];"
        : "=r"(r[0]), "=r"(r[1]), "=r"(r[2]), "=r"(r[3])
        : "r"(addr));
}

static __device__ __forceinline__ uint32_t smem_u32(const void* p) {
    uint32_t a;
    asm("{ .reg .u64 t; cvta.to.shared.u64 t, %1; cvt.u32.u64 %0, t; }"
        : "=r"(a) : "l"(p));
    return a;
}

// pack two floats to bf16x2: low half = lo, high half = hi (rn rounding)
static __device__ __forceinline__ uint32_t pack_bf16x2(float lo, float hi) {
    uint32_t r;
    asm("cvt.rn.bf16x2.f32 %0, %1, %2;" : "=r"(r) : "f"(hi), "f"(lo));
    return r;
}
static __device__ __forceinline__ float bf16lo_f(uint32_t r) {
    return __uint_as_float(r << 16);
}
static __device__ __forceinline__ float bf16hi_f(uint32_t r) {
    return __uint_as_float(r & 0xFFFF0000u);
}

// ===========================================================================
// Transpose: x[b][C][HW] -> g_xT[b][HW][C]  (float4 both directions)
// ===========================================================================
__global__ __launch_bounds__(256) void transpose_x_kernel(const float* __restrict__ x)
{
    __shared__ float sm[32][33];
    const int z = blockIdx.z;
    const int hw0 = blockIdx.x * 32, c0 = blockIdx.y * 32;
    const float* xz = x + (size_t)z * CIN * HW;
    float* tz = g_xT + (size_t)z * HW * CIN;
    const int t = threadIdx.x;

    {
        int c = t >> 3, h4 = (t & 7) * 4;
        float4 v = *(const float4*)&xz[(size_t)(c0 + c) * HW + hw0 + h4];
        sm[c][h4 + 0] = v.x; sm[c][h4 + 1] = v.y;
        sm[c][h4 + 2] = v.z; sm[c][h4 + 3] = v.w;
    }
    __syncthreads();
    {
        int h = t >> 3, c4 = (t & 7) * 4;
        float4 v;
        v.x = sm[c4 + 0][h]; v.y = sm[c4 + 1][h];
        v.z = sm[c4 + 2][h]; v.w = sm[c4 + 3][h];
        *(float4*)&tz[(size_t)(hw0 + h) * CIN + c0 + c4] = v;
    }
}

// ===========================================================================
// bf16x3-split tensor-core GEMM (unchanged from round 7).
// C[z][M][HW] = A(MxK) @ B[z](HWxK)^T + bias.
// mode 0: B = g_xT,    C = g_qkv ; mode 1: B = g_attnT, C = Cext.
// ===========================================================================
#define RSB   80          // bytes per smem row (32 bf16 used + pad)
#define RSW   20          // uint32 per smem row
#define ABUF  10240       // one operand array: 128 rows * 80B
#define SMBUF 40960       // Ahi,Alo,Bhi,Blo
#define GEMM_SMEM (2 * SMBUF)   // 81920; epilogue stage (128*130*4) fits

__global__ __launch_bounds__(256) void gemm_bf16x3_kernel(
    const float* __restrict__ A, const float* __restrict__ bias,
    float* __restrict__ Cext, int mode)
{
    extern __shared__ char dynsm[];
    const uint32_t sbase = smem_u32(dynsm);

    const int tid  = threadIdx.x;
    const int lane = tid & 31;
    const int wid  = tid >> 5;
    const int m0 = blockIdx.x * 128;
    const int n0 = blockIdx.y * 128;
    const int z  = blockIdx.z;

    const float* Bz = ((mode == 0) ? g_xT : g_attnT) + (size_t)z * HW * KDIM;
    float* C = (mode == 0) ? (g_qkv + (size_t)z * C3 * HW)
                           : (Cext  + (size_t)z * CQ * HW);
    const float* Ag = A  + (size_t)m0 * KDIM;
    const float* Bg = Bz + (size_t)n0 * KDIM;

    const int mbase = (wid & 3) * 32;
    const int nbase = (wid >> 2) * 64;

    const int row_a  = (lane & 7) + ((lane >> 3) & 1) * 8;
    const int kboff_a = (lane >> 4) * 16;
    const int row_b  = (lane & 7) + (lane >> 4) * 8;
    const int kboff_b = ((lane >> 3) & 1) * 16;

    float acc[2][8][4];
    #pragma unroll
    for (int i = 0; i < 2; i++)
        #pragma unroll
        for (int j = 0; j < 8; j++)
            #pragma unroll
            for (int r = 0; r < 4; r++) acc[i][j][r] = 0.f;

    float4 pa[4], pb[4];

#define CV_STORE(arrHiOff, arrLoOff, rowi, k4i, v) do {                       \
        uint32_t h0 = pack_bf16x2((v).x, (v).y);                              \
        uint32_t h1 = pack_bf16x2((v).z, (v).w);                              \
        float l0 = (v).x - bf16lo_f(h0);                                      \
        float l1 = (v).y - bf16hi_f(h0);                                      \
        float l2 = (v).z - bf16lo_f(h1);                                      \
        float l3 = (v).w - bf16hi_f(h1);                                      \
        uint32_t* hp = (uint32_t*)(dynsm + bufOff + (arrHiOff))               \
                       + (rowi) * RSW + (k4i) * 2;                            \
        uint32_t* lp = (uint32_t*)(dynsm + bufOff + (arrLoOff))               \
                       + (rowi) * RSW + (k4i) * 2;                            \
        hp[0] = h0; hp[1] = h1;                                               \
        lp[0] = pack_bf16x2(l0, l1); lp[1] = pack_bf16x2(l2, l3);             \
    } while (0)

    {
        const int bufOff = 0;
        #pragma unroll
        for (int i = 0; i < 4; i++) {
            int idx = tid + i * 256;
            int r = idx >> 3, k4 = idx & 7;
            float4 va = *(const float4*)&Ag[(size_t)r * KDIM + k4 * 4];
            float4 vb = *(const float4*)&Bg[(size_t)r * KDIM + k4 * 4];
            CV_STORE(0, ABUF, r, k4, va);
            CV_STORE(2 * ABUF, 3 * ABUF, r, k4, vb);
        }
    }
    __syncthreads();

    int cur = 0;
    for (int s = 0; s < NSLAB; s++) {
        if (s + 1 < NSLAB) {
            const int k0 = (s + 1) * 32;
            #pragma unroll
            for (int i = 0; i < 4; i++) {
                int idx = tid + i * 256;
                int r = idx >> 3, k4 = idx & 7;
                pa[i] = *(const float4*)&Ag[(size_t)r * KDIM + k0 + k4 * 4];
                pb[i] = *(const float4*)&Bg[(size_t)r * KDIM + k0 + k4 * 4];
            }
        }

        const uint32_t base = sbase + cur * SMBUF;
        #pragma unroll
        for (int kc = 0; kc < 2; kc++) {
            const int kb = kc * 32;
            uint32_t af[2][4], al[2][4], bf[4][4];
            #pragma unroll
            for (int i = 0; i < 2; i++) {
                uint32_t ra = base + (mbase + i * 16 + row_a) * RSB + kb + kboff_a;
                ldm4(af[i], ra);
                ldm4(al[i], ra + ABUF);
            }
            #pragma unroll
            for (int p = 0; p < 4; p++) {
                uint32_t rb = base + 2 * ABUF
                            + (nbase + p * 16 + row_b) * RSB + kb + kboff_b;
                ldm4(bf[p], rb);
            }
            #pragma unroll
            for (int i = 0; i < 2; i++)
                #pragma unroll
                for (int j = 0; j < 8; j++)
                    mma_bf16(acc[i][j], af[i], &bf[j >> 1][(j & 1) * 2]);
            #pragma unroll
            for (int i = 0; i < 2; i++)
                #pragma unroll
                for (int j = 0; j < 8; j++)
                    mma_bf16(acc[i][j], al[i], &bf[j >> 1][(j & 1) * 2]);
            #pragma unroll
            for (int p = 0; p < 4; p++) {
                uint32_t rb = base + 3 * ABUF
                            + (nbase + p * 16 + row_b) * RSB + kb + kboff_b;
                ldm4(bf[p], rb);
            }
            #pragma unroll
            for (int i = 0; i < 2; i++)
                #pragma unroll
                for (int j = 0; j < 8; j++)
                    mma_bf16(acc[i][j], af[i], &bf[j >> 1][(j & 1) * 2]);
        }

        if (s + 1 < NSLAB) {
            const int bufOff = (cur ^ 1) * SMBUF;
            #pragma unroll
            for (int i = 0; i < 4; i++) {
                int idx = tid + i * 256;
                int r = idx >> 3, k4 = idx & 7;
                CV_STORE(0, ABUF, r, k4, pa[i]);
                CV_STORE(2 * ABUF, 3 * ABUF, r, k4, pb[i]);
            }
        }
        __syncthreads();
        cur ^= 1;
    }

    float* stage = (float*)dynsm;   // [128][130]
    #pragma unroll
    for (int i = 0; i < 2; i++) {
        #pragma unroll
        for (int j = 0; j < 8; j++) {
            int r = mbase + i * 16 + (lane >> 2);
            int c = nbase + j * 8 + (lane & 3) * 2;
            stage[r * 130 + c]           = acc[i][j][0];
            stage[r * 130 + c + 1]       = acc[i][j][1];
            stage[(r + 8) * 130 + c]     = acc[i][j][2];
            stage[(r + 8) * 130 + c + 1] = acc[i][j][3];
        }
    }
    __syncthreads();

    #pragma unroll
    for (int it = 0; it < 16; it++) {
        const int m = it * 8 + wid;
        const float bi = bias[m0 + m];
        float* crow = &C[(size_t)(m0 + m) * HW + n0];
        #pragma unroll
        for (int jj = 0; jj < 4; jj++) {
            int n = (tid & 31) + jj * 32;
            crow[n] = stage[m * 130 + n] + bi;
        }
    }
#undef CV_STORE
}

// ===========================================================================
// Window MHA v3: float4 gmem loads (window rows are 32B-contiguous; 4-pixel
// groups uniformly in/out of bounds in the shifted branch), STS.128 q/k.
// 4x4 microtile compute; output token-major g_attnT.
// ===========================================================================
template <int SHIFT, int NW>
__global__ __launch_bounds__(256) void wattn_kernel()
{
    __shared__ float q_sm[64 * 64];  // [d][n]; reused as P[r][j]
    __shared__ float k_sm[64 * 64];  // [d][n]
    __shared__ float v_sm[64 * 64];  // [n][d ^ ((n&15)<<2)]

    const int tid  = threadIdx.x;
    const int widx = blockIdx.x;
    const int head = blockIdx.y;
    const int b    = blockIdx.z;
    const int wy = widx / NW, wx = widx % NW;
    const int y0 = wy * 8 - SHIFT, x0 = wx * 8 - SHIFT;

    const float* base = g_qkv + (size_t)b * C3 * HW;
    const int chq = head * HD;

    #pragma unroll
    for (int it = 0; it < 4; it++) {
        int i = tid + it * 256;          // 0..1023
        int d = i >> 4, g = i & 15;      // d 0..63, n-group 0..15
        int y = y0 + (g >> 1);
        int xg = x0 + (g & 1) * 4;       // aligned 4-pixel group
        float4 qv = make_float4(0.f, 0.f, 0.f, 0.f);
        float4 kv = qv, vv = qv;
        if (SHIFT == 0 || ((unsigned)y < H_ && (unsigned)xg < W_)) {
            size_t poff = (size_t)y * W_ + xg;
            qv = *(const float4*)&base[(size_t)(chq + d) * HW + poff];
            kv = *(const float4*)&base[(size_t)(CQ + chq + d) * HW + poff];
            vv = *(const float4*)&base[(size_t)(2 * CQ + chq + d) * HW + poff];
        }
        int n = g * 4;
        *(float4*)&q_sm[d * 64 + n] = qv;
        *(float4*)&k_sm[d * 64 + n] = kv;
        v_sm[(n + 0) * 64 + (d ^ (((n + 0) & 15) << 2))] = vv.x;
        v_sm[(n + 1) * 64 + (d ^ (((n + 1) & 15) << 2))] = vv.y;
        v_sm[(n + 2) * 64 + (d ^ (((n + 2) & 15) << 2))] = vv.z;
        v_sm[(n + 3) * 64 + (d ^ (((n + 3) & 15) << 2))] = vv.w;
    }
    __syncthreads();

    const int tc = tid & 15;
    const int tr = tid >> 4;
    const int r0 = tr * 4, c0 = tc * 4;

    float s[4][4];
    #pragma unroll
    for (int i = 0; i < 4; i++)
        #pragma unroll
        for (int j = 0; j < 4; j++) s[i][j] = 0.f;

    for (int d = 0; d < 64; d++) {
        float4 qv = *(const float4*)&q_sm[d * 64 + r0];
        float4 kv = *(const float4*)&k_sm[d * 64 + c0];
        float qa[4] = {qv.x, qv.y, qv.z, qv.w};
        float ka[4] = {kv.x, kv.y, kv.z, kv.w};
        #pragma unroll
        for (int i = 0; i < 4; i++)
            #pragma unroll
            for (int j = 0; j < 4; j++)
                s[i][j] += qa[i] * ka[j];
    }

    const float scale = 0.125f;
    float inv[4];
    #pragma unroll
    for (int i = 0; i < 4; i++) {
        float m = fmaxf(fmaxf(s[i][0], s[i][1]), fmaxf(s[i][2], s[i][3]));
        m = fmaxf(m, __shfl_xor_sync(0xffffffffu, m, 1));
        m = fmaxf(m, __shfl_xor_sync(0xffffffffu, m, 2));
        m = fmaxf(m, __shfl_xor_sync(0xffffffffu, m, 4));
        m = fmaxf(m, __shfl_xor_sync(0xffffffffu, m, 8));
        float sum = 0.f;
        #pragma unroll
        for (int j = 0; j < 4; j++) {
            s[i][j] = __expf((s[i][j] - m) * scale);
            sum += s[i][j];
        }
        sum += __shfl_xor_sync(0xffffffffu, sum, 1);
        sum += __shfl_xor_sync(0xffffffffu, sum, 2);
        sum += __shfl_xor_sync(0xffffffffu, sum, 4);
        sum += __shfl_xor_sync(0xffffffffu, sum, 8);
        inv[i] = 1.f / sum;
    }

    __syncthreads();

    #pragma unroll
    for (int i = 0; i < 4; i++) {
        float4 p4;
        p4.x = s[i][0] * inv[i]; p4.y = s[i][1] * inv[i];
        p4.z = s[i][2] * inv[i]; p4.w = s[i][3] * inv[i];
        *(float4*)&q_sm[(r0 + i) * 64 + c0] = p4;
    }
    __syncthreads();

    float o[4][4];
    #pragma unroll
    for (int i = 0; i < 4; i++)
        #pragma unroll
        for (int j = 0; j < 4; j++) o[i][j] = 0.f;

    for (int j0 = 0; j0 < 64; j0 += 4) {
        float4 p4[4];
        #pragma unroll
        for (int i = 0; i < 4; i++)
            p4[i] = *(const float4*)&q_sm[(r0 + i) * 64 + j0];
        #pragma unroll
        for (int jj = 0; jj < 4; jj++) {
            int j = j0 + jj;
            float4 vv = *(const float4*)&v_sm[j * 64 + (c0 ^ ((j & 15) << 2))];
            float pj[4] = {p4[0].x, p4[1].x, p4[2].x, p4[3].x};
            if (jj == 1) { pj[0]=p4[0].y; pj[1]=p4[1].y; pj[2]=p4[2].y; pj[3]=p4[3].y; }
            if (jj == 2) { pj[0]=p4[0].z; pj[1]=p4[1].z; pj[2]=p4[2].z; pj[3]=p4[3].z; }
            if (jj == 3) { pj[0]=p4[0].w; pj[1]=p4[1].w; pj[2]=p4[2].w; pj[3]=p4[3].w; }
            #pragma unroll
            for (int i = 0; i < 4; i++) {
                o[i][0] += pj[i] * vv.x; o[i][1] += pj[i] * vv.y;
                o[i][2] += pj[i] * vv.z; o[i][3] += pj[i] * vv.w;
            }
        }
    }

    #pragma unroll
    for (int i = 0; i < 4; i++) {
        int n = r0 + i;
        int y = y0 + (n >> 3), x = x0 + (n & 7);
        if (SHIFT == 0 || ((unsigned)y < H_ && (unsigned)x < W_)) {
            float* op = g_attnT + ((size_t)b * HW + (size_t)y * W_ + x) * CQ
                      + chq + c0;
            if (SHIFT) {
                op[0] += o[i][0]; op[1] += o[i][1];
                op[2] += o[i][2]; op[3] += o[i][3];
            } else {
                float4 w4;
                w4.x = o[i][0]; w4.y = o[i][1]; w4.z = o[i][2]; w4.w = o[i][3];
                *(float4*)op = w4;
            }
        }
    }
}

// ---------------------------------------------------------------------------
extern "C" void kernel_launch(void* const* d_in, const int* in_sizes, int n_in,
                              void* d_out, int out_size)
{
    (void)in_sizes; (void)n_in; (void)out_size;
    const float* x      = (const float*)d_in[0];
    const float* w_qkv  = (const float*)d_in[1];
    const float* b_qkv  = (const float*)d_in[2];
    const float* w_head = (const float*)d_in[3];
    const float* b_head = (const float*)d_in[4];
    float* out = (float*)d_out;

    cudaFuncSetAttribute(gemm_bf16x3_kernel,
                         cudaFuncAttributeMaxDynamicSharedMemorySize, GEMM_SMEM);

    // 0) transpose x -> g_xT [b][hw][c]
    {
        dim3 grid(HW / 32, CIN / 32, NB);
        transpose_x_kernel<<<grid, 256>>>(x);
    }
    // 1) qkv = w_qkv @ x + b_qkv  (M=1152)
    {
        dim3 grid(C3 / 128, HW / 128, NB);
        gemm_bf16x3_kernel<<<grid, 256, GEMM_SMEM>>>(w_qkv, b_qkv, nullptr, 0);
    }
    // 2) branch 1: aligned windows (writes g_attnT)
    {
        dim3 grid(16 * 16, NH, NB);
        wattn_kernel<0, 16><<<grid, 256>>>();
    }
    // 3) branch 2: shifted windows with zero-pad (accumulates into g_attnT)
    {
        dim3 grid(17 * 17, NH, NB);
        wattn_kernel<4, 17><<<grid, 256>>>();
    }
    // 4) out = w_head @ (x1+x2) + b_head  (M=384)
    {
        dim3 grid(CQ / 128, HW / 128, NB);
        gemm_bf16x3_kernel<<<grid, 256, GEMM_SMEM>>>(w_head, b_head, out, 1);
    }
}

// round 11
// speedup vs baseline: 1.4366x; 1.4366x over previous
#include <cuda_runtime.h>
#include <cstdint>

#define H_ 128
#define W_ 128
#define HW 16384
#define CIN 384
#define CQ 384
#define C3 1152
#define NH 6
#define HD 64
#define NB 4
#define KDIM 384          // K for both GEMMs
#define NSLAB 12          // 384 / 32

// Scratch (no allocation allowed). NOTE: device globals are ONLY referenced
// from device code — never passed as kernel arguments from the host (host
// shadow-symbol addresses silently alias host memory via ATS on GB300).
__device__ float    g_xT    [(size_t)NB * HW * CIN];  // x^T fp32 [b][hw][c]
__device__ float    g_qkv   [(size_t)NB * C3 * HW];   // qkv [b][c3][hw]
__device__ float    g_attnT [(size_t)NB * HW * CQ];   // branch-1 out [b][hw][c]
__device__ float    g_attnT2[(size_t)NB * HW * CQ];   // branch-2 out [b][hw][c]
__device__ uint16_t g_wq_hi [C3 * KDIM];              // w_qkv bf16 hi
__device__ uint16_t g_wq_lo [C3 * KDIM];
__device__ uint16_t g_wh_hi [CQ * KDIM];              // w_head bf16 hi
__device__ uint16_t g_wh_lo [CQ * KDIM];

// ===========================================================================
// helpers (baseline PTX, valid for every sm_103 gencode pass)
// ===========================================================================
static __device__ __forceinline__ void mma_bf16(
    float* d, const uint32_t* a, const uint32_t* b)
{
    asm volatile(
        "mma.sync.aligned.m16n8k16.row.col.f32.bf16.bf16.f32 "
        "{%0,%1,%2,%3}, {%4,%5,%6,%7}, {%8,%9}, {%0,%1,%2,%3};"
        : "+f"(d[0]), "+f"(d[1]), "+f"(d[2]), "+f"(d[3])
        : "r"(a[0]), "r"(a[1]), "r"(a[2]), "r"(a[3]),
          "r"(b[0]), "r"(b[1]));
}

static __device__ __forceinline__ void ldm4(uint32_t* r, uint32_t addr)
{
    asm volatile(
        "ldmatrix.sync.aligned.m8n8.x4.shared.b16 {%0,%1,%2,%3}, [%4];"
        : "=r"(r[0]), "=r"(r[1]), "=r"(r[2]), "=r"(r[3])
        : "r"(addr));
}

static __device__ __forceinline__ uint32_t smem_u32(const void* p) {
    uint32_t a;
    asm("{ .reg .u64 t; cvta.to.shared.u64 t, %1; cvt.u32.u64 %0, t; }"
        : "=r"(a) : "l"(p));
    return a;
}

// pack two floats to bf16x2: low half <- first arg, high half <- second
static __device__ __forceinline__ uint32_t pack_bf16x2(float lo, float hi) {
    uint32_t r;
    asm("cvt.rn.bf16x2.f32 %0, %1, %2;" : "=r"(r) : "f"(hi), "f"(lo));
    return r;
}
static __device__ __forceinline__ float bf16lo_f(uint32_t r) {
    return __uint_as_float(r << 16);
}
static __device__ __forceinline__ float bf16hi_f(uint32_t r) {
    return __uint_as_float(r & 0xFFFF0000u);
}

// ===========================================================================
// prep: split a weight matrix (fp32) into bf16 hi/lo. Target arrays are
// selected in DEVICE code via `which` (0 = w_qkv, 1 = w_head).
// ===========================================================================
__global__ __launch_bounds__(256) void prep_w_kernel(
    const float* __restrict__ w, int which, int n4)
{
    uint16_t* hi = which ? g_wh_hi : g_wq_hi;
    uint16_t* lo = which ? g_wh_lo : g_wq_lo;
    int i = blockIdx.x * 256 + threadIdx.x;
    if (i >= n4) return;
    float4 v = ((const float4*)w)[i];
    uint2 h, l;
    h.x = pack_bf16x2(v.x, v.y);
    h.y = pack_bf16x2(v.z, v.w);
    l.x = pack_bf16x2(v.x - bf16lo_f(h.x), v.y - bf16hi_f(h.x));
    l.y = pack_bf16x2(v.z - bf16lo_f(h.y), v.w - bf16hi_f(h.y));
    ((uint2*)hi)[i] = h;
    ((uint2*)lo)[i] = l;
}

// ===========================================================================
// Transpose: x[b][C][HW] -> g_xT[b][HW][C]  (round-7 exact)
// ===========================================================================
__global__ __launch_bounds__(256) void transpose_x_kernel(const float* __restrict__ x)
{
    __shared__ float sm[32][33];
    const int z = blockIdx.z;
    const int hw0 = blockIdx.x * 32, c0 = blockIdx.y * 32;
    const float* xz = x + (size_t)z * CIN * HW;
    float* tz = g_xT + (size_t)z * HW * CIN;
    const int tx = threadIdx.x & 31, ty = threadIdx.x >> 5;

    #pragma unroll
    for (int i = 0; i < 4; i++)
        sm[ty + 8 * i][tx] = xz[(size_t)(c0 + ty + 8 * i) * HW + hw0 + tx];
    __syncthreads();
    #pragma unroll
    for (int i = 0; i < 4; i++)
        tz[(size_t)(hw0 + ty + 8 * i) * CIN + c0 + tx] = sm[tx][ty + 8 * i];
}

// ===========================================================================
// bf16x3-split tensor-core GEMM (round-7 core; A operand pre-split).
// C[z][M][HW] = A(MxK) @ B[z](HWxK)^T + bias.
// mode 0: A = g_wq (split), B = g_xT,              C = g_qkv
// mode 1: A = g_wh (split), B = g_attnT+g_attnT2,  C = Cext
// ===========================================================================
#define RSB   80          // bytes per smem row (64B data + 16 pad)
#define ABUF  10240       // one operand array: 128 rows * 80B
#define SMBUF 40960       // Ahi,Alo,Bhi,Blo
#define GEMM_SMEM (2 * SMBUF)

__global__ __launch_bounds__(256) void gemm_bf16x3_kernel(
    const float* __restrict__ bias, float* __restrict__ Cext, int mode)
{
    extern __shared__ char dynsm[];
    const uint32_t sbase = smem_u32(dynsm);

    const int tid  = threadIdx.x;
    const int lane = tid & 31;
    const int wid  = tid >> 5;
    const int m0 = blockIdx.x * 128;
    const int n0 = blockIdx.y * 128;
    const int z  = blockIdx.z;

    const uint16_t* Ahi = (mode == 0) ? g_wq_hi : g_wh_hi;
    const uint16_t* Alo = (mode == 0) ? g_wq_lo : g_wh_lo;
    const float* B1 = ((mode == 0) ? g_xT : g_attnT) + (size_t)z * HW * KDIM;
    const float* B2 = g_attnT2 + (size_t)z * HW * KDIM;
    float* C = (mode == 0) ? (g_qkv + (size_t)z * C3 * HW)
                           : (Cext  + (size_t)z * CQ * HW);

    // A loader: 256 threads cover 128 rows x 32 bf16 per array via uint4
    const int r_ld = tid >> 2;           // 0..63 (and +64)
    const int c_ld = (tid & 3) * 8;      // bf16 element offset {0,8,16,24}
    const uint16_t* pAhi0 = &Ahi[(size_t)(m0 + r_ld) * KDIM + c_ld];
    const uint16_t* pAhi1 = &Ahi[(size_t)(m0 + r_ld + 64) * KDIM + c_ld];
    const uint16_t* pAlo0 = &Alo[(size_t)(m0 + r_ld) * KDIM + c_ld];
    const uint16_t* pAlo1 = &Alo[(size_t)(m0 + r_ld + 64) * KDIM + c_ld];
    const uint32_t aoff0 = (uint32_t)(r_ld * RSB + (tid & 3) * 16);
    const uint32_t aoff1 = aoff0 + 64 * RSB;

    const float* Bg1 = B1 + (size_t)n0 * KDIM;
    const float* Bg2 = B2 + (size_t)n0 * KDIM;

    const int mbase = (wid & 3) * 32;
    const int nbase = (wid >> 2) * 64;

    const int row_a  = (lane & 7) + ((lane >> 3) & 1) * 8;
    const int kboff_a = (lane >> 4) * 16;
    const int row_b  = (lane & 7) + (lane >> 4) * 8;
    const int kboff_b = ((lane >> 3) & 1) * 16;

    float acc[2][8][4];
    #pragma unroll
    for (int i = 0; i < 2; i++)
        #pragma unroll
        for (int j = 0; j < 8; j++)
            #pragma unroll
            for (int r = 0; r < 4; r++) acc[i][j][r] = 0.f;

    uint4  qa[4];   // A prefetch: Ahi0, Ahi1, Alo0, Alo1
    float4 pb[4];   // B prefetch (already summed for mode 1)

#define A_LOAD(k0) do {                                                       \
        qa[0] = *(const uint4*)(pAhi0 + (k0));                                \
        qa[1] = *(const uint4*)(pAhi1 + (k0));                                \
        qa[2] = *(const uint4*)(pAlo0 + (k0));                                \
        qa[3] = *(const uint4*)(pAlo1 + (k0));                                \
    } while (0)

#define A_STORE(bufOff) do {                                                  \
        char* st = dynsm + (bufOff);                                          \
        *(uint4*)(st + aoff0)        = qa[0];                                 \
        *(uint4*)(st + aoff1)        = qa[1];                                 \
        *(uint4*)(st + ABUF + aoff0) = qa[2];                                 \
        *(uint4*)(st + ABUF + aoff1) = qa[3];                                 \
    } while (0)

#define B_LOAD(k0) do {                                                       \
        _Pragma("unroll")                                                     \
        for (int i = 0; i < 4; i++) {                                         \
            int idx = tid + i * 256;                                          \
            int r = idx >> 3, k4 = idx & 7;                                   \
            float4 v = *(const float4*)&Bg1[(size_t)r * KDIM + (k0) + k4 * 4];\
            if (mode) {                                                       \
                float4 t = *(const float4*)&Bg2[(size_t)r * KDIM + (k0) + k4 * 4];\
                v.x += t.x; v.y += t.y; v.z += t.z; v.w += t.w;               \
            }                                                                 \
            pb[i] = v;                                                        \
        }                                                                     \
    } while (0)

#define B_STORE(bufOff) do {                                                  \
        _Pragma("unroll")                                                     \
        for (int i = 0; i < 4; i++) {                                         \
            int idx = tid + i * 256;                                          \
            int r = idx >> 3, k4 = idx & 7;                                   \
            float4 v = pb[i];                                                 \
            uint32_t h0 = pack_bf16x2(v.x, v.y);                              \
            uint32_t h1 = pack_bf16x2(v.z, v.w);                              \
            uint32_t l0 = pack_bf16x2(v.x - bf16lo_f(h0), v.y - bf16hi_f(h0));\
            uint32_t l1 = pack_bf16x2(v.z - bf16lo_f(h1), v.w - bf16hi_f(h1));\
            uint32_t* hp = (uint32_t*)(dynsm + (bufOff) + 2 * ABUF)           \
                           + r * (RSB / 4) + k4 * 2;                          \
            uint32_t* lp = (uint32_t*)(dynsm + (bufOff) + 3 * ABUF)           \
                           + r * (RSB / 4) + k4 * 2;                          \
            hp[0] = h0; hp[1] = h1;                                           \
            lp[0] = l0; lp[1] = l1;                                           \
        }                                                                     \
    } while (0)

    A_LOAD(0); B_LOAD(0);
    A_STORE(0); B_STORE(0);
    __syncthreads();

    int cur = 0;
    for (int s = 0; s < NSLAB; s++) {
        if (s + 1 < NSLAB) { A_LOAD((s + 1) * 32); B_LOAD((s + 1) * 32); }

        const uint32_t base = sbase + cur * SMBUF;
        #pragma unroll
        for (int kc = 0; kc < 2; kc++) {
            const int kb = kc * 32;
            uint32_t af[2][4], al[2][4], bf[4][4];
            #pragma unroll
            for (int i = 0; i < 2; i++) {
                uint32_t ra_ = base + (mbase + i * 16 + row_a) * RSB + kb + kboff_a;
                ldm4(af[i], ra_);
                ldm4(al[i], ra_ + ABUF);
            }
            #pragma unroll
            for (int p = 0; p < 4; p++) {
                uint32_t rb_ = base + 2 * ABUF
                             + (nbase + p * 16 + row_b) * RSB + kb + kboff_b;
                ldm4(bf[p], rb_);
            }
            #pragma unroll
            for (int i = 0; i < 2; i++)
                #pragma unroll
                for (int j = 0; j < 8; j++)
                    mma_bf16(acc[i][j], af[i], &bf[j >> 1][(j & 1) * 2]);
            #pragma unroll
            for (int i = 0; i < 2; i++)
                #pragma unroll
                for (int j = 0; j < 8; j++)
                    mma_bf16(acc[i][j], al[i], &bf[j >> 1][(j & 1) * 2]);
            #pragma unroll
            for (int p = 0; p < 4; p++) {
                uint32_t rb_ = base + 3 * ABUF
                             + (nbase + p * 16 + row_b) * RSB + kb + kboff_b;
                ldm4(bf[p], rb_);
            }
            #pragma unroll
            for (int i = 0; i < 2; i++)
                #pragma unroll
                for (int j = 0; j < 8; j++)
                    mma_bf16(acc[i][j], af[i], &bf[j >> 1][(j & 1) * 2]);
        }

        if (s + 1 < NSLAB) { A_STORE((cur ^ 1) * SMBUF); B_STORE((cur ^ 1) * SMBUF); }
        __syncthreads();
        cur ^= 1;
    }

    // epilogue: frags -> smem stage -> coalesced global + bias
    float* stage = (float*)dynsm;   // [128][130]
    #pragma unroll
    for (int i = 0; i < 2; i++) {
        #pragma unroll
        for (int j = 0; j < 8; j++) {
            int r = mbase + i * 16 + (lane >> 2);
            int c = nbase + j * 8 + (lane & 3) * 2;
            stage[r * 130 + c]           = acc[i][j][0];
            stage[r * 130 + c + 1]       = acc[i][j][1];
            stage[(r + 8) * 130 + c]     = acc[i][j][2];
            stage[(r + 8) * 130 + c + 1] = acc[i][j][3];
        }
    }
    __syncthreads();

    #pragma unroll
    for (int it = 0; it < 16; it++) {
        const int m = it * 8 + wid;
        const float bi = bias[m0 + m];
        float* crow = &C[(size_t)(m0 + m) * HW + n0];
        #pragma unroll
        for (int jj = 0; jj < 4; jj++) {
            int n = (tid & 31) + jj * 32;
            crow[n] = stage[m * 130 + n] + bi;
        }
    }
#undef A_LOAD
#undef A_STORE
#undef B_LOAD
#undef B_STORE
}

// ===========================================================================
// Window MHA (round-7 exact compute). SHIFT=0 -> g_attnT, SHIFT=4 -> g_attnT2
// (both plain float4 stores; buffers summed by the head GEMM).
// Merged into one launch: blockIdx.x < 256 selects branch 1.
// ===========================================================================
template <int SHIFT, int NW>
static __device__ __forceinline__ void wattn_body(
    int widx, float* q_sm, float* k_sm, float* v_sm)
{
    const int tid  = threadIdx.x;
    const int head = blockIdx.y;
    const int b    = blockIdx.z;
    const int wy = widx / NW, wx = widx % NW;
    const int y0 = wy * 8 - SHIFT, x0 = wx * 8 - SHIFT;

    const float* base = g_qkv + (size_t)b * C3 * HW;
    const int chq = head * HD;

    #pragma unroll
    for (int it = 0; it < 16; it++) {
        int idx = tid + it * 256;        // idx = d*64 + n
        int d = idx >> 6, n = idx & 63;
        int y = y0 + (n >> 3), x = x0 + (n & 7);
        float qv = 0.f, kv = 0.f, vv = 0.f;
        if (SHIFT == 0 || ((unsigned)y < H_ && (unsigned)x < W_)) {
            size_t poff = (size_t)y * W_ + x;
            qv = base[(size_t)(chq + d) * HW + poff];
            kv = base[(size_t)(CQ + chq + d) * HW + poff];
            vv = base[(size_t)(2 * CQ + chq + d) * HW + poff];
        }
        q_sm[idx] = qv;
        k_sm[idx] = kv;
        v_sm[n * 64 + (d ^ ((n & 15) << 2))] = vv;
    }
    __syncthreads();

    const int tc = tid & 15;
    const int tr = tid >> 4;
    const int r0 = tr * 4, c0 = tc * 4;

    float s[4][4];
    #pragma unroll
    for (int i = 0; i < 4; i++)
        #pragma unroll
        for (int j = 0; j < 4; j++) s[i][j] = 0.f;

    for (int d = 0; d < 64; d++) {
        float4 qv = *(const float4*)&q_sm[d * 64 + r0];
        float4 kv = *(const float4*)&k_sm[d * 64 + c0];
        float qa[4] = {qv.x, qv.y, qv.z, qv.w};
        float ka[4] = {kv.x, kv.y, kv.z, kv.w};
        #pragma unroll
        for (int i = 0; i < 4; i++)
            #pragma unroll
            for (int j = 0; j < 4; j++)
                s[i][j] += qa[i] * ka[j];
    }

    const float scale = 0.125f;
    float inv[4];
    #pragma unroll
    for (int i = 0; i < 4; i++) {
        float m = fmaxf(fmaxf(s[i][0], s[i][1]), fmaxf(s[i][2], s[i][3]));
        m = fmaxf(m, __shfl_xor_sync(0xffffffffu, m, 1));
        m = fmaxf(m, __shfl_xor_sync(0xffffffffu, m, 2));
        m = fmaxf(m, __shfl_xor_sync(0xffffffffu, m, 4));
        m = fmaxf(m, __shfl_xor_sync(0xffffffffu, m, 8));
        float sum = 0.f;
        #pragma unroll
        for (int j = 0; j < 4; j++) {
            s[i][j] = __expf((s[i][j] - m) * scale);
            sum += s[i][j];
        }
        sum += __shfl_xor_sync(0xffffffffu, sum, 1);
        sum += __shfl_xor_sync(0xffffffffu, sum, 2);
        sum += __shfl_xor_sync(0xffffffffu, sum, 4);
        sum += __shfl_xor_sync(0xffffffffu, sum, 8);
        inv[i] = 1.f / sum;
    }

    __syncthreads();

    #pragma unroll
    for (int i = 0; i < 4; i++) {
        float4 p4;
        p4.x = s[i][0] * inv[i]; p4.y = s[i][1] * inv[i];
        p4.z = s[i][2] * inv[i]; p4.w = s[i][3] * inv[i];
        *(float4*)&q_sm[(r0 + i) * 64 + c0] = p4;
    }
    __syncthreads();

    float o[4][4];
    #pragma unroll
    for (int i = 0; i < 4; i++)
        #pragma unroll
        for (int j = 0; j < 4; j++) o[i][j] = 0.f;

    for (int j0 = 0; j0 < 64; j0 += 4) {
        float4 p4[4];
        #pragma unroll
        for (int i = 0; i < 4; i++)
            p4[i] = *(const float4*)&q_sm[(r0 + i) * 64 + j0];
        #pragma unroll
        for (int jj = 0; jj < 4; jj++) {
            int j = j0 + jj;
            float4 vv = *(const float4*)&v_sm[j * 64 + (c0 ^ ((j & 15) << 2))];
            float pj[4] = {p4[0].x, p4[1].x, p4[2].x, p4[3].x};
            if (jj == 1) { pj[0]=p4[0].y; pj[1]=p4[1].y; pj[2]=p4[2].y; pj[3]=p4[3].y; }
            if (jj == 2) { pj[0]=p4[0].z; pj[1]=p4[1].z; pj[2]=p4[2].z; pj[3]=p4[3].z; }
            if (jj == 3) { pj[0]=p4[0].w; pj[1]=p4[1].w; pj[2]=p4[2].w; pj[3]=p4[3].w; }
            #pragma unroll
            for (int i = 0; i < 4; i++) {
                o[i][0] += pj[i] * vv.x; o[i][1] += pj[i] * vv.y;
                o[i][2] += pj[i] * vv.z; o[i][3] += pj[i] * vv.w;
            }
        }
    }

    float* outbuf = (SHIFT == 0) ? g_attnT : g_attnT2;
    #pragma unroll
    for (int i = 0; i < 4; i++) {
        int n = r0 + i;
        int y = y0 + (n >> 3), x = x0 + (n & 7);
        if (SHIFT == 0 || ((unsigned)y < H_ && (unsigned)x < W_)) {
            float* op = outbuf + ((size_t)b * HW + (size_t)y * W_ + x) * CQ
                      + chq + c0;
            float4 w4;
            w4.x = o[i][0]; w4.y = o[i][1]; w4.z = o[i][2]; w4.w = o[i][3];
            *(float4*)op = w4;
        }
    }
}

__global__ __launch_bounds__(256) void wattn_all_kernel()
{
    __shared__ float q_sm[64 * 64];
    __shared__ float k_sm[64 * 64];
    __shared__ float v_sm[64 * 64];
    if (blockIdx.x < 256)
        wattn_body<0, 16>(blockIdx.x, q_sm, k_sm, v_sm);
    else
        wattn_body<4, 17>(blockIdx.x - 256, q_sm, k_sm, v_sm);
}

// ---------------------------------------------------------------------------
extern "C" void kernel_launch(void* const* d_in, const int* in_sizes, int n_in,
                              void* d_out, int out_size)
{
    (void)in_sizes; (void)n_in; (void)out_size;
    const float* x      = (const float*)d_in[0];
    const float* w_qkv  = (const float*)d_in[1];
    const float* b_qkv  = (const float*)d_in[2];
    const float* w_head = (const float*)d_in[3];
    const float* b_head = (const float*)d_in[4];
    float* out = (float*)d_out;

    cudaFuncSetAttribute(gemm_bf16x3_kernel,
                         cudaFuncAttributeMaxDynamicSharedMemorySize, GEMM_SMEM);

    // 0a) split weights to bf16 hi/lo (device-side symbol selection!)
    prep_w_kernel<<<(C3 * KDIM / 4 + 255) / 256, 256>>>(w_qkv, 0, C3 * KDIM / 4);
    prep_w_kernel<<<(CQ * KDIM / 4 + 255) / 256, 256>>>(w_head, 1, CQ * KDIM / 4);
    // 0b) transpose x -> g_xT [b][hw][c]
    {
        dim3 grid(HW / 32, CIN / 32, NB);
        transpose_x_kernel<<<grid, 256>>>(x);
    }
    // 1) qkv = w_qkv @ x + b_qkv  (M=1152)
    {
        dim3 grid(C3 / 128, HW / 128, NB);
        gemm_bf16x3_kernel<<<grid, 256, GEMM_SMEM>>>(b_qkv, nullptr, 0);
    }
    // 2+3) both window-attention branches, one launch (independent buffers)
    {
        dim3 grid(256 + 289, NH, NB);
        wattn_all_kernel<<<grid, 256>>>();
    }
    // 4) out = w_head @ (x1+x2) + b_head  (M=384; B = attnT + attnT2)
    {
        dim3 grid(CQ / 128, HW / 128, NB);
        gemm_bf16x3_kernel<<<grid, 256, GEMM_SMEM>>>(b_head, out, 1);
    }
}

// round 12
// speedup vs baseline: 1.6044x; 1.1168x over previous
#include <cuda_runtime.h>
#include <cstdint>

#define H_ 128
#define W_ 128
#define HW 16384
#define CIN 384
#define CQ 384
#define C3 1152
#define NH 6
#define HD 64
#define NB 4
#define KDIM 384          // K for both GEMMs
#define NSLAB 12          // 384 / 32

// Scratch (no allocation allowed). RULE: device globals are referenced ONLY
// from device code — never passed as kernel args from host (ATS makes the
// host shadow symbol silently writable -> zero-filled device arrays).
__device__ float    g_qkv   [(size_t)NB * C3 * HW];   // qkv [b][c3][hw]
__device__ float    g_attnT [(size_t)NB * HW * CQ];   // branch-1 out (fp32)
__device__ float    g_attnT2[(size_t)NB * HW * CQ];   // branch-2 out (fp32)
__device__ uint16_t g_xb_hi [(size_t)NB * HW * CIN];  // x^T bf16 hi [b][hw][c]
__device__ uint16_t g_xb_lo [(size_t)NB * HW * CIN];
__device__ uint16_t g_at_hi [(size_t)NB * HW * CQ];   // (attn1+attn2) bf16 hi
__device__ uint16_t g_at_lo [(size_t)NB * HW * CQ];
__device__ uint16_t g_wq_hi [C3 * KDIM];
__device__ uint16_t g_wq_lo [C3 * KDIM];
__device__ uint16_t g_wh_hi [CQ * KDIM];
__device__ uint16_t g_wh_lo [CQ * KDIM];

// ===========================================================================
// helpers (baseline PTX, valid in every sm_103 gencode pass)
// ===========================================================================
static __device__ __forceinline__ void mma_bf16(
    float* d, const uint32_t* a, const uint32_t* b)
{
    asm volatile(
        "mma.sync.aligned.m16n8k16.row.col.f32.bf16.bf16.f32 "
        "{%0,%1,%2,%3}, {%4,%5,%6,%7}, {%8,%9}, {%0,%1,%2,%3};"
        : "+f"(d[0]), "+f"(d[1]), "+f"(d[2]), "+f"(d[3])
        : "r"(a[0]), "r"(a[1]), "r"(a[2]), "r"(a[3]),
          "r"(b[0]), "r"(b[1]));
}

static __device__ __forceinline__ void ldm4(uint32_t* r, uint32_t addr)
{
    asm volatile(
        "ldmatrix.sync.aligned.m8n8.x4.shared.b16 {%0,%1,%2,%3}, [%4];"
        : "=r"(r[0]), "=r"(r[1]), "=r"(r[2]), "=r"(r[3])
        : "r"(addr));
}

static __device__ __forceinline__ uint32_t smem_u32(const void* p) {
    uint32_t a;
    asm("{ .reg .u64 t; cvta.to.shared.u64 t, %1; cvt.u32.u64 %0, t; }"
        : "=r"(a) : "l"(p));
    return a;
}

static __device__ __forceinline__ uint32_t pack_bf16x2(float lo, float hi) {
    uint32_t r;
    asm("cvt.rn.bf16x2.f32 %0, %1, %2;" : "=r"(r) : "f"(hi), "f"(lo));
    return r;
}
static __device__ __forceinline__ float bf16lo_f(uint32_t r) {
    return __uint_as_float(r << 16);
}
static __device__ __forceinline__ float bf16hi_f(uint32_t r) {
    return __uint_as_float(r & 0xFFFF0000u);
}

#define CP_ASYNC16(sa, gp) \
    asm volatile("cp.async.cg.shared.global [%0], [%1], 16;" :: "r"(sa), "l"(gp))
#define CP_COMMIT() asm volatile("cp.async.commit_group;" ::: "memory")
#define CP_WAIT(n)  asm volatile("cp.async.wait_group %0;" :: "n"(n) : "memory")

// ===========================================================================
// prep: split weights into bf16 hi/lo (device-side target selection)
// ===========================================================================
__global__ __launch_bounds__(256) void prep_w_kernel(
    const float* __restrict__ w, int which, int n4)
{
    uint16_t* hi = which ? g_wh_hi : g_wq_hi;
    uint16_t* lo = which ? g_wh_lo : g_wq_lo;
    int i = blockIdx.x * 256 + threadIdx.x;
    if (i >= n4) return;
    float4 v = ((const float4*)w)[i];
    uint2 h, l;
    h.x = pack_bf16x2(v.x, v.y);
    h.y = pack_bf16x2(v.z, v.w);
    l.x = pack_bf16x2(v.x - bf16lo_f(h.x), v.y - bf16hi_f(h.x));
    l.y = pack_bf16x2(v.z - bf16lo_f(h.y), v.w - bf16hi_f(h.y));
    ((uint2*)hi)[i] = h;
    ((uint2*)lo)[i] = l;
}

// ===========================================================================
// Transpose + split: x[b][C][HW] -> g_xb_hi/lo [b][hw][c]
// ===========================================================================
__global__ __launch_bounds__(256) void transpose_x_kernel(const float* __restrict__ x)
{
    __shared__ float sm[32][33];
    const int z = blockIdx.z;
    const int hw0 = blockIdx.x * 32, c0 = blockIdx.y * 32;
    const float* xz = x + (size_t)z * CIN * HW;
    uint16_t* th = g_xb_hi + (size_t)z * HW * CIN;
    uint16_t* tl = g_xb_lo + (size_t)z * HW * CIN;
    const int t = threadIdx.x;
    const int tx = t & 31, ty = t >> 5;

    #pragma unroll
    for (int i = 0; i < 4; i++)
        sm[ty + 8 * i][tx] = xz[(size_t)(c0 + ty + 8 * i) * HW + hw0 + tx];
    __syncthreads();

    {
        int h = t >> 3, cp = (t & 7) * 4;
        float v0 = sm[cp + 0][h], v1 = sm[cp + 1][h];
        float v2 = sm[cp + 2][h], v3 = sm[cp + 3][h];
        uint2 hi, lo;
        hi.x = pack_bf16x2(v0, v1);
        hi.y = pack_bf16x2(v2, v3);
        lo.x = pack_bf16x2(v0 - bf16lo_f(hi.x), v1 - bf16hi_f(hi.x));
        lo.y = pack_bf16x2(v2 - bf16lo_f(hi.y), v3 - bf16hi_f(hi.y));
        size_t off = (size_t)(hw0 + h) * CIN + c0 + cp;
        *(uint2*)&th[off] = hi;
        *(uint2*)&tl[off] = lo;
    }
}

// ===========================================================================
// sum + split: g_at_hi/lo = split(g_attnT + g_attnT2)
// ===========================================================================
__global__ __launch_bounds__(256) void sum_split_kernel()
{
    int i = blockIdx.x * 256 + threadIdx.x;   // float4 index
    float4 a = ((const float4*)g_attnT)[i];
    float4 b = ((const float4*)g_attnT2)[i];
    float v0 = a.x + b.x, v1 = a.y + b.y, v2 = a.z + b.z, v3 = a.w + b.w;
    uint2 h, l;
    h.x = pack_bf16x2(v0, v1);
    h.y = pack_bf16x2(v2, v3);
    l.x = pack_bf16x2(v0 - bf16lo_f(h.x), v1 - bf16hi_f(h.x));
    l.y = pack_bf16x2(v2 - bf16lo_f(h.y), v3 - bf16hi_f(h.y));
    ((uint2*)g_at_hi)[i] = h;
    ((uint2*)g_at_lo)[i] = l;
}

// ===========================================================================
// bf16x3-split tensor-core GEMM; ALL operands pre-split bf16 in gmem.
// cp.async double-buffered mainloop (no conversions, no prefetch registers),
// 2 CTAs/SM via __launch_bounds__(256, 2).
// C[z][M][HW] = A(MxK) @ B[z](HWxK)^T + bias.
// mode 0: A = g_wq, B = g_xb, C = g_qkv ; mode 1: A = g_wh, B = g_at, C = Cext
// ===========================================================================
#define RSB   80          // bytes per smem row (64B data + 16 pad)
#define ABUF  10240       // one operand array: 128 rows * 80B
#define SMBUF 40960       // Ahi,Alo,Bhi,Blo per stage
#define GEMM_SMEM (2 * SMBUF)

__global__ __launch_bounds__(256, 2) void gemm_bf16x3_kernel(
    const float* __restrict__ bias, float* __restrict__ Cext, int mode)
{
    extern __shared__ char dynsm[];
    const uint32_t sbase = smem_u32(dynsm);

    const int tid  = threadIdx.x;
    const int lane = tid & 31;
    const int wid  = tid >> 5;
    const int m0 = blockIdx.x * 128;
    const int n0 = blockIdx.y * 128;
    const int z  = blockIdx.z;

    const uint16_t* Ahi = (mode == 0) ? g_wq_hi : g_wh_hi;
    const uint16_t* Alo = (mode == 0) ? g_wq_lo : g_wh_lo;
    const uint16_t* Bhi = ((mode == 0) ? g_xb_hi : g_at_hi) + (size_t)z * HW * KDIM;
    const uint16_t* Blo = ((mode == 0) ? g_xb_lo : g_at_lo) + (size_t)z * HW * KDIM;
    float* C = (mode == 0) ? (g_qkv + (size_t)z * C3 * HW)
                           : (Cext  + (size_t)z * CQ * HW);

    // cp.async chunk map: 2048 16B-chunks per slab (4 arrays x 128 rows x 4).
    // Thread handles chunks id = i*256 + tid, i<8. Precompute gmem row ptrs
    // (sans k-offset) and smem offsets (sans buffer offset).
    const uint16_t* gptr[8];
    uint32_t soff[8];
    #pragma unroll
    for (int i = 0; i < 8; i++) {
        int id  = i * 256 + tid;
        int arr = id >> 9;           // 0 Ahi, 1 Alo, 2 Bhi, 3 Blo
        int idx = id & 511;
        int r   = idx >> 2;
        int q   = idx & 3;
        const uint16_t* base =
            (arr == 0) ? Ahi + (size_t)(m0 + r) * KDIM :
            (arr == 1) ? Alo + (size_t)(m0 + r) * KDIM :
            (arr == 2) ? Bhi + (size_t)(n0 + r) * KDIM :
                         Blo + (size_t)(n0 + r) * KDIM;
        gptr[i] = base + q * 8;
        soff[i] = (uint32_t)(arr * ABUF + r * RSB + q * 16);
    }

#define ISSUE_SLAB(k0, bufOff) do {                                           \
        _Pragma("unroll")                                                     \
        for (int i = 0; i < 8; i++)                                           \
            CP_ASYNC16(sbase + (bufOff) + soff[i], gptr[i] + (k0));           \
        CP_COMMIT();                                                          \
    } while (0)

    const int mbase = (wid & 3) * 32;
    const int nbase = (wid >> 2) * 64;
    const int row_a  = (lane & 7) + ((lane >> 3) & 1) * 8;
    const int kboff_a = (lane >> 4) * 16;
    const int row_b  = (lane & 7) + (lane >> 4) * 8;
    const int kboff_b = ((lane >> 3) & 1) * 16;

    float acc[2][8][4];
    #pragma unroll
    for (int i = 0; i < 2; i++)
        #pragma unroll
        for (int j = 0; j < 8; j++)
            #pragma unroll
            for (int r = 0; r < 4; r++) acc[i][j][r] = 0.f;

    ISSUE_SLAB(0, 0);

    int cur = 0;
    for (int s = 0; s < NSLAB; s++) {
        if (s + 1 < NSLAB) {
            ISSUE_SLAB((s + 1) * 32, (cur ^ 1) * SMBUF);
            CP_WAIT(1);
        } else {
            CP_WAIT(0);
        }
        __syncthreads();

        const uint32_t base = sbase + cur * SMBUF;
        #pragma unroll
        for (int kc = 0; kc < 2; kc++) {
            const int kb = kc * 32;
            uint32_t af[2][4], al[2][4], bf[4][4];
            #pragma unroll
            for (int i = 0; i < 2; i++) {
                uint32_t ra_ = base + (mbase + i * 16 + row_a) * RSB + kb + kboff_a;
                ldm4(af[i], ra_);
                ldm4(al[i], ra_ + ABUF);
            }
            #pragma unroll
            for (int p = 0; p < 4; p++) {
                uint32_t rb_ = base + 2 * ABUF
                             + (nbase + p * 16 + row_b) * RSB + kb + kboff_b;
                ldm4(bf[p], rb_);
            }
            #pragma unroll
            for (int i = 0; i < 2; i++)
                #pragma unroll
                for (int j = 0; j < 8; j++)
                    mma_bf16(acc[i][j], af[i], &bf[j >> 1][(j & 1) * 2]);
            #pragma unroll
            for (int i = 0; i < 2; i++)
                #pragma unroll
                for (int j = 0; j < 8; j++)
                    mma_bf16(acc[i][j], al[i], &bf[j >> 1][(j & 1) * 2]);
            #pragma unroll
            for (int p = 0; p < 4; p++) {
                uint32_t rb_ = base + 3 * ABUF
                             + (nbase + p * 16 + row_b) * RSB + kb + kboff_b;
                ldm4(bf[p], rb_);
            }
            #pragma unroll
            for (int i = 0; i < 2; i++)
                #pragma unroll
                for (int j = 0; j < 8; j++)
                    mma_bf16(acc[i][j], af[i], &bf[j >> 1][(j & 1) * 2]);
        }
        __syncthreads();   // reads done before next slab overwrites this buf
        cur ^= 1;
    }

    // epilogue: frags -> smem stage -> coalesced global + bias
    float* stage = (float*)dynsm;   // [128][130] = 66560B, fits
    #pragma unroll
    for (int i = 0; i < 2; i++) {
        #pragma unroll
        for (int j = 0; j < 8; j++) {
            int r = mbase + i * 16 + (lane >> 2);
            int c = nbase + j * 8 + (lane & 3) * 2;
            stage[r * 130 + c]           = acc[i][j][0];
            stage[r * 130 + c + 1]       = acc[i][j][1];
            stage[(r + 8) * 130 + c]     = acc[i][j][2];
            stage[(r + 8) * 130 + c + 1] = acc[i][j][3];
        }
    }
    __syncthreads();

    #pragma unroll
    for (int it = 0; it < 16; it++) {
        const int m = it * 8 + wid;
        const float bi = bias[m0 + m];
        float* crow = &C[(size_t)(m0 + m) * HW + n0];
        #pragma unroll
        for (int jj = 0; jj < 4; jj++) {
            int n = (tid & 31) + jj * 32;
            crow[n] = stage[m * 130 + n] + bi;
        }
    }
#undef ISSUE_SLAB
}

// ===========================================================================
// Window MHA (round-7 exact compute). SHIFT=0 -> g_attnT, SHIFT=4 -> g_attnT2.
// Merged into one launch: blockIdx.x < 256 selects branch 1.
// ===========================================================================
template <int SHIFT, int NW>
static __device__ __forceinline__ void wattn_body(
    int widx, float* q_sm, float* k_sm, float* v_sm)
{
    const int tid  = threadIdx.x;
    const int head = blockIdx.y;
    const int b    = blockIdx.z;
    const int wy = widx / NW, wx = widx % NW;
    const int y0 = wy * 8 - SHIFT, x0 = wx * 8 - SHIFT;

    const float* base = g_qkv + (size_t)b * C3 * HW;
    const int chq = head * HD;

    #pragma unroll
    for (int it = 0; it < 16; it++) {
        int idx = tid + it * 256;        // idx = d*64 + n
        int d = idx >> 6, n = idx & 63;
        int y = y0 + (n >> 3), x = x0 + (n & 7);
        float qv = 0.f, kv = 0.f, vv = 0.f;
        if (SHIFT == 0 || ((unsigned)y < H_ && (unsigned)x < W_)) {
            size_t poff = (size_t)y * W_ + x;
            qv = base[(size_t)(chq + d) * HW + poff];
            kv = base[(size_t)(CQ + chq + d) * HW + poff];
            vv = base[(size_t)(2 * CQ + chq + d) * HW + poff];
        }
        q_sm[idx] = qv;
        k_sm[idx] = kv;
        v_sm[n * 64 + (d ^ ((n & 15) << 2))] = vv;
    }
    __syncthreads();

    const int tc = tid & 15;
    const int tr = tid >> 4;
    const int r0 = tr * 4, c0 = tc * 4;

    float s[4][4];
    #pragma unroll
    for (int i = 0; i < 4; i++)
        #pragma unroll
        for (int j = 0; j < 4; j++) s[i][j] = 0.f;

    for (int d = 0; d < 64; d++) {
        float4 qv = *(const float4*)&q_sm[d * 64 + r0];
        float4 kv = *(const float4*)&k_sm[d * 64 + c0];
        float qa[4] = {qv.x, qv.y, qv.z, qv.w};
        float ka[4] = {kv.x, kv.y, kv.z, kv.w};
        #pragma unroll
        for (int i = 0; i < 4; i++)
            #pragma unroll
            for (int j = 0; j < 4; j++)
                s[i][j] += qa[i] * ka[j];
    }

    const float scale = 0.125f;
    float inv[4];
    #pragma unroll
    for (int i = 0; i < 4; i++) {
        float m = fmaxf(fmaxf(s[i][0], s[i][1]), fmaxf(s[i][2], s[i][3]));
        m = fmaxf(m, __shfl_xor_sync(0xffffffffu, m, 1));
        m = fmaxf(m, __shfl_xor_sync(0xffffffffu, m, 2));
        m = fmaxf(m, __shfl_xor_sync(0xffffffffu, m, 4));
        m = fmaxf(m, __shfl_xor_sync(0xffffffffu, m, 8));
        float sum = 0.f;
        #pragma unroll
        for (int j = 0; j < 4; j++) {
            s[i][j] = __expf((s[i][j] - m) * scale);
            sum += s[i][j];
        }
        sum += __shfl_xor_sync(0xffffffffu, sum, 1);
        sum += __shfl_xor_sync(0xffffffffu, sum, 2);
        sum += __shfl_xor_sync(0xffffffffu, sum, 4);
        sum += __shfl_xor_sync(0xffffffffu, sum, 8);
        inv[i] = 1.f / sum;
    }

    __syncthreads();

    #pragma unroll
    for (int i = 0; i < 4; i++) {
        float4 p4;
        p4.x = s[i][0] * inv[i]; p4.y = s[i][1] * inv[i];
        p4.z = s[i][2] * inv[i]; p4.w = s[i][3] * inv[i];
        *(float4*)&q_sm[(r0 + i) * 64 + c0] = p4;
    }
    __syncthreads();

    float o[4][4];
    #pragma unroll
    for (int i = 0; i < 4; i++)
        #pragma unroll
        for (int j = 0; j < 4; j++) o[i][j] = 0.f;

    for (int j0 = 0; j0 < 64; j0 += 4) {
        float4 p4[4];
        #pragma unroll
        for (int i = 0; i < 4; i++)
            p4[i] = *(const float4*)&q_sm[(r0 + i) * 64 + j0];
        #pragma unroll
        for (int jj = 0; jj < 4; jj++) {
            int j = j0 + jj;
            float4 vv = *(const float4*)&v_sm[j * 64 + (c0 ^ ((j & 15) << 2))];
            float pj[4] = {p4[0].x, p4[1].x, p4[2].x, p4[3].x};
            if (jj == 1) { pj[0]=p4[0].y; pj[1]=p4[1].y; pj[2]=p4[2].y; pj[3]=p4[3].y; }
            if (jj == 2) { pj[0]=p4[0].z; pj[1]=p4[1].z; pj[2]=p4[2].z; pj[3]=p4[3].z; }
            if (jj == 3) { pj[0]=p4[0].w; pj[1]=p4[1].w; pj[2]=p4[2].w; pj[3]=p4[3].w; }
            #pragma unroll
            for (int i = 0; i < 4; i++) {
                o[i][0] += pj[i] * vv.x; o[i][1] += pj[i] * vv.y;
                o[i][2] += pj[i] * vv.z; o[i][3] += pj[i] * vv.w;
            }
        }
    }

    float* outbuf = (SHIFT == 0) ? g_attnT : g_attnT2;
    #pragma unroll
    for (int i = 0; i < 4; i++) {
        int n = r0 + i;
        int y = y0 + (n >> 3), x = x0 + (n & 7);
        if (SHIFT == 0 || ((unsigned)y < H_ && (unsigned)x < W_)) {
            float* op = outbuf + ((size_t)b * HW + (size_t)y * W_ + x) * CQ
                      + chq + c0;
            float4 w4;
            w4.x = o[i][0]; w4.y = o[i][1]; w4.z = o[i][2]; w4.w = o[i][3];
            *(float4*)op = w4;
        }
    }
}

__global__ __launch_bounds__(256) void wattn_all_kernel()
{
    __shared__ float q_sm[64 * 64];
    __shared__ float k_sm[64 * 64];
    __shared__ float v_sm[64 * 64];
    if (blockIdx.x < 256)
        wattn_body<0, 16>(blockIdx.x, q_sm, k_sm, v_sm);
    else
        wattn_body<4, 17>(blockIdx.x - 256, q_sm, k_sm, v_sm);
}

// ---------------------------------------------------------------------------
extern "C" void kernel_launch(void* const* d_in, const int* in_sizes, int n_in,
                              void* d_out, int out_size)
{
    (void)in_sizes; (void)n_in; (void)out_size;
    const float* x      = (const float*)d_in[0];
    const float* w_qkv  = (const float*)d_in[1];
    const float* b_qkv  = (const float*)d_in[2];
    const float* w_head = (const float*)d_in[3];
    const float* b_head = (const float*)d_in[4];
    float* out = (float*)d_out;

    cudaFuncSetAttribute(gemm_bf16x3_kernel,
                         cudaFuncAttributeMaxDynamicSharedMemorySize, GEMM_SMEM);

    // 0a) split weights (device-side symbol selection)
    prep_w_kernel<<<(C3 * KDIM / 4 + 255) / 256, 256>>>(w_qkv, 0, C3 * KDIM / 4);
    prep_w_kernel<<<(CQ * KDIM / 4 + 255) / 256, 256>>>(w_head, 1, CQ * KDIM / 4);
    // 0b) transpose + split x -> g_xb_hi/lo [b][hw][c]
    {
        dim3 grid(HW / 32, CIN / 32, NB);
        transpose_x_kernel<<<grid, 256>>>(x);
    }
    // 1) qkv = w_qkv @ x + b_qkv  (M=1152)
    {
        dim3 grid(C3 / 128, HW / 128, NB);
        gemm_bf16x3_kernel<<<grid, 256, GEMM_SMEM>>>(b_qkv, nullptr, 0);
    }
    // 2+3) both window-attention branches, one launch
    {
        dim3 grid(256 + 289, NH, NB);
        wattn_all_kernel<<<grid, 256>>>();
    }
    // 3b) sum branches + split to bf16 hi/lo
    sum_split_kernel<<<(int)((size_t)NB * HW * CQ / 4 / 256), 256>>>();
    // 4) out = w_head @ (x1+x2) + b_head  (M=384)
    {
        dim3 grid(CQ / 128, HW / 128, NB);
        gemm_bf16x3_kernel<<<grid, 256, GEMM_SMEM>>>(b_head, out, 1);
    }
}

// round 13
// speedup vs baseline: 1.7661x; 1.1008x over previous
#include <cuda_runtime.h>
#include <cstdint>

#define H_ 128
#define W_ 128
#define HW 16384
#define CIN 384
#define CQ 384
#define C3 1152
#define NH 6
#define HD 64
#define NB 4
#define KDIM 384          // K for both GEMMs
#define NSLAB 12          // 384 / 32

// Scratch (no allocation allowed). RULE: device globals are referenced ONLY
// from device code — never passed as kernel args from host (ATS makes the
// host shadow symbol silently writable -> zero-filled device arrays).
__device__ float    g_qkv   [(size_t)NB * C3 * HW];   // qkv [b][c3][hw]
__device__ float    g_attnT [(size_t)NB * HW * CQ];   // branch-1 out (fp32)
__device__ float    g_attnT2[(size_t)NB * HW * CQ];   // branch-2 out (fp32)
__device__ uint16_t g_xb_hi [(size_t)NB * HW * CIN];  // x^T bf16 hi [b][hw][c]
__device__ uint16_t g_xb_lo [(size_t)NB * HW * CIN];
__device__ uint16_t g_at_hi [(size_t)NB * HW * CQ];   // (attn1+attn2) bf16 hi
__device__ uint16_t g_at_lo [(size_t)NB * HW * CQ];
__device__ uint16_t g_wq_hi [C3 * KDIM];
__device__ uint16_t g_wq_lo [C3 * KDIM];
__device__ uint16_t g_wh_hi [CQ * KDIM];
__device__ uint16_t g_wh_lo [CQ * KDIM];

// ===========================================================================
// helpers (baseline PTX, valid in every sm_103 gencode pass)
// ===========================================================================
static __device__ __forceinline__ void mma_bf16(
    float* d, const uint32_t* a, const uint32_t* b)
{
    asm volatile(
        "mma.sync.aligned.m16n8k16.row.col.f32.bf16.bf16.f32 "
        "{%0,%1,%2,%3}, {%4,%5,%6,%7}, {%8,%9}, {%0,%1,%2,%3};"
        : "+f"(d[0]), "+f"(d[1]), "+f"(d[2]), "+f"(d[3])
        : "r"(a[0]), "r"(a[1]), "r"(a[2]), "r"(a[3]),
          "r"(b[0]), "r"(b[1]));
}

static __device__ __forceinline__ void ldm4(uint32_t* r, uint32_t addr)
{
    asm volatile(
        "ldmatrix.sync.aligned.m8n8.x4.shared.b16 {%0,%1,%2,%3}, [%4];"
        : "=r"(r[0]), "=r"(r[1]), "=r"(r[2]), "=r"(r[3])
        : "r"(addr));
}

static __device__ __forceinline__ uint32_t smem_u32(const void* p) {
    uint32_t a;
    asm("{ .reg .u64 t; cvta.to.shared.u64 t, %1; cvt.u32.u64 %0, t; }"
        : "=r"(a) : "l"(p));
    return a;
}

static __device__ __forceinline__ uint32_t pack_bf16x2(float lo, float hi) {
    uint32_t r;
    asm("cvt.rn.bf16x2.f32 %0, %1, %2;" : "=r"(r) : "f"(hi), "f"(lo));
    return r;
}
static __device__ __forceinline__ float bf16lo_f(uint32_t r) {
    return __uint_as_float(r << 16);
}
static __device__ __forceinline__ float bf16hi_f(uint32_t r) {
    return __uint_as_float(r & 0xFFFF0000u);
}

#define CP_ASYNC16(sa, gp) \
    asm volatile("cp.async.cg.shared.global [%0], [%1], 16;" :: "r"(sa), "l"(gp))
#define CP_COMMIT() asm volatile("cp.async.commit_group;" ::: "memory")
#define CP_WAIT(n)  asm volatile("cp.async.wait_group %0;" :: "n"(n) : "memory")

// ===========================================================================
// prep: split weights into bf16 hi/lo (device-side target selection)
// ===========================================================================
__global__ __launch_bounds__(256) void prep_w_kernel(
    const float* __restrict__ w, int which, int n4)
{
    uint16_t* hi = which ? g_wh_hi : g_wq_hi;
    uint16_t* lo = which ? g_wh_lo : g_wq_lo;
    int i = blockIdx.x * 256 + threadIdx.x;
    if (i >= n4) return;
    float4 v = ((const float4*)w)[i];
    uint2 h, l;
    h.x = pack_bf16x2(v.x, v.y);
    h.y = pack_bf16x2(v.z, v.w);
    l.x = pack_bf16x2(v.x - bf16lo_f(h.x), v.y - bf16hi_f(h.x));
    l.y = pack_bf16x2(v.z - bf16lo_f(h.y), v.w - bf16hi_f(h.y));
    ((uint2*)hi)[i] = h;
    ((uint2*)lo)[i] = l;
}

// ===========================================================================
// Transpose + split: x[b][C][HW] -> g_xb_hi/lo [b][hw][c]
// ===========================================================================
__global__ __launch_bounds__(256) void transpose_x_kernel(const float* __restrict__ x)
{
    __shared__ float sm[32][33];
    const int z = blockIdx.z;
    const int hw0 = blockIdx.x * 32, c0 = blockIdx.y * 32;
    const float* xz = x + (size_t)z * CIN * HW;
    uint16_t* th = g_xb_hi + (size_t)z * HW * CIN;
    uint16_t* tl = g_xb_lo + (size_t)z * HW * CIN;
    const int t = threadIdx.x;
    const int tx = t & 31, ty = t >> 5;

    #pragma unroll
    for (int i = 0; i < 4; i++)
        sm[ty + 8 * i][tx] = xz[(size_t)(c0 + ty + 8 * i) * HW + hw0 + tx];
    __syncthreads();

    {
        int h = t >> 3, cp = (t & 7) * 4;
        float v0 = sm[cp + 0][h], v1 = sm[cp + 1][h];
        float v2 = sm[cp + 2][h], v3 = sm[cp + 3][h];
        uint2 hi, lo;
        hi.x = pack_bf16x2(v0, v1);
        hi.y = pack_bf16x2(v2, v3);
        lo.x = pack_bf16x2(v0 - bf16lo_f(hi.x), v1 - bf16hi_f(hi.x));
        lo.y = pack_bf16x2(v2 - bf16lo_f(hi.y), v3 - bf16hi_f(hi.y));
        size_t off = (size_t)(hw0 + h) * CIN + c0 + cp;
        *(uint2*)&th[off] = hi;
        *(uint2*)&tl[off] = lo;
    }
}

// ===========================================================================
// sum + split: g_at_hi/lo = split(g_attnT + g_attnT2)
// ===========================================================================
__global__ __launch_bounds__(256) void sum_split_kernel()
{
    int i = blockIdx.x * 256 + threadIdx.x;   // float4 index
    float4 a = ((const float4*)g_attnT)[i];
    float4 b = ((const float4*)g_attnT2)[i];
    float v0 = a.x + b.x, v1 = a.y + b.y, v2 = a.z + b.z, v3 = a.w + b.w;
    uint2 h, l;
    h.x = pack_bf16x2(v0, v1);
    h.y = pack_bf16x2(v2, v3);
    l.x = pack_bf16x2(v0 - bf16lo_f(h.x), v1 - bf16hi_f(h.x));
    l.y = pack_bf16x2(v2 - bf16lo_f(h.y), v3 - bf16hi_f(h.y));
    ((uint2*)g_at_hi)[i] = h;
    ((uint2*)g_at_lo)[i] = l;
}

// ===========================================================================
// bf16x3-split tensor-core GEMM; pre-split operands, cp.async 3-stage
// pipeline, XOR-swizzled smem (no pad), ONE barrier per K-slab, 2 CTAs/SM.
// C[z][M][HW] = A(MxK) @ B[z](HWxK)^T + bias.
// mode 0: A = g_wq, B = g_xb, C = g_qkv ; mode 1: A = g_wh, B = g_at, C = Cext
// Swizzle: 16B chunk c within a 64B row r is stored at c ^ ((r>>1)&3).
// ===========================================================================
#define RSB   64          // bytes per smem row (no pad; swizzled)
#define ABUF  8192        // one operand array: 128 rows * 64B
#define SMBUF 32768       // Ahi,Alo,Bhi,Blo per stage
#define NSTG  3
#define GEMM_SMEM (NSTG * SMBUF)   // 98304 -> 2 CTAs/SM

__global__ __launch_bounds__(256, 2) void gemm_bf16x3_kernel(
    const float* __restrict__ bias, float* __restrict__ Cext, int mode)
{
    extern __shared__ char dynsm[];
    const uint32_t sbase = smem_u32(dynsm);

    const int tid  = threadIdx.x;
    const int lane = tid & 31;
    const int wid  = tid >> 5;
    const int m0 = blockIdx.x * 128;
    const int n0 = blockIdx.y * 128;
    const int z  = blockIdx.z;

    const uint16_t* Ahi = (mode == 0) ? g_wq_hi : g_wh_hi;
    const uint16_t* Alo = (mode == 0) ? g_wq_lo : g_wh_lo;
    const uint16_t* Bhi = ((mode == 0) ? g_xb_hi : g_at_hi) + (size_t)z * HW * KDIM;
    const uint16_t* Blo = ((mode == 0) ? g_xb_lo : g_at_lo) + (size_t)z * HW * KDIM;
    float* C = (mode == 0) ? (g_qkv + (size_t)z * C3 * HW)
                           : (Cext  + (size_t)z * CQ * HW);

    // cp.async chunk map: 2048 16B-chunks per slab (4 arrays x 128 rows x 4).
    const uint16_t* gptr[8];
    uint32_t soff[8];
    #pragma unroll
    for (int i = 0; i < 8; i++) {
        int id  = i * 256 + tid;
        int arr = id >> 9;           // 0 Ahi, 1 Alo, 2 Bhi, 3 Blo
        int idx = id & 511;
        int r   = idx >> 2;
        int q   = idx & 3;
        const uint16_t* base =
            (arr == 0) ? Ahi + (size_t)(m0 + r) * KDIM :
            (arr == 1) ? Alo + (size_t)(m0 + r) * KDIM :
            (arr == 2) ? Bhi + (size_t)(n0 + r) * KDIM :
                         Blo + (size_t)(n0 + r) * KDIM;
        gptr[i] = base + q * 8;
        soff[i] = (uint32_t)(arr * ABUF + r * RSB + ((q ^ ((r >> 1) & 3)) * 16));
    }

#define ISSUE_SLAB(k0, bufOff) do {                                           \
        _Pragma("unroll")                                                     \
        for (int i = 0; i < 8; i++)                                           \
            CP_ASYNC16(sbase + (bufOff) + soff[i], gptr[i] + (k0));           \
        CP_COMMIT();                                                          \
    } while (0)

    const int mbase = (wid & 3) * 32;
    const int nbase = (wid >> 2) * 64;
    const int row_a = (lane & 7) + ((lane >> 3) & 1) * 8;
    const int qa_hi = lane >> 4;              // chunk sub-index for A
    const int row_b = (lane & 7) + (lane >> 4) * 8;
    const int qb_hi = (lane >> 3) & 1;        // chunk sub-index for B

    float acc[2][8][4];
    #pragma unroll
    for (int i = 0; i < 2; i++)
        #pragma unroll
        for (int j = 0; j < 8; j++)
            #pragma unroll
            for (int r = 0; r < 4; r++) acc[i][j][r] = 0.f;

    // prologue: stage slabs 0 and 1
    ISSUE_SLAB(0, 0);
    ISSUE_SLAB(32, SMBUF);

    for (int s = 0; s < NSLAB; s++) {
        if (s + 1 < NSLAB) CP_WAIT(1);
        else               CP_WAIT(0);
        __syncthreads();
        if (s + 2 < NSLAB) ISSUE_SLAB((s + 2) * 32, ((s + 2) % NSTG) * SMBUF);

        const uint32_t base = sbase + (s % NSTG) * SMBUF;
        #pragma unroll
        for (int kc = 0; kc < 2; kc++) {
            uint32_t af[2][4], al[2][4], bf[4][4];
            #pragma unroll
            for (int i = 0; i < 2; i++) {
                int rw = mbase + i * 16 + row_a;
                uint32_t c = (uint32_t)((2 * kc + qa_hi) ^ ((rw >> 1) & 3));
                uint32_t ra_ = base + rw * RSB + c * 16;
                ldm4(af[i], ra_);
                ldm4(al[i], ra_ + ABUF);
            }
            #pragma unroll
            for (int p = 0; p < 4; p++) {
                int rw = nbase + p * 16 + row_b;
                uint32_t c = (uint32_t)((2 * kc + qb_hi) ^ ((rw >> 1) & 3));
                ldm4(bf[p], base + 2 * ABUF + rw * RSB + c * 16);
            }
            #pragma unroll
            for (int i = 0; i < 2; i++)
                #pragma unroll
                for (int j = 0; j < 8; j++)
                    mma_bf16(acc[i][j], af[i], &bf[j >> 1][(j & 1) * 2]);
            #pragma unroll
            for (int i = 0; i < 2; i++)
                #pragma unroll
                for (int j = 0; j < 8; j++)
                    mma_bf16(acc[i][j], al[i], &bf[j >> 1][(j & 1) * 2]);
            #pragma unroll
            for (int p = 0; p < 4; p++) {
                int rw = nbase + p * 16 + row_b;
                uint32_t c = (uint32_t)((2 * kc + qb_hi) ^ ((rw >> 1) & 3));
                ldm4(bf[p], base + 3 * ABUF + rw * RSB + c * 16);
            }
            #pragma unroll
            for (int i = 0; i < 2; i++)
                #pragma unroll
                for (int j = 0; j < 8; j++)
                    mma_bf16(acc[i][j], af[i], &bf[j >> 1][(j & 1) * 2]);
        }
    }
    __syncthreads();   // all compute done before stage reuse

    // epilogue: frags -> smem stage -> coalesced global + bias
    float* stage = (float*)dynsm;   // [128][130] = 66560B <= 98304
    #pragma unroll
    for (int i = 0; i < 2; i++) {
        #pragma unroll
        for (int j = 0; j < 8; j++) {
            int r = mbase + i * 16 + (lane >> 2);
            int c = nbase + j * 8 + (lane & 3) * 2;
            stage[r * 130 + c]           = acc[i][j][0];
            stage[r * 130 + c + 1]       = acc[i][j][1];
            stage[(r + 8) * 130 + c]     = acc[i][j][2];
            stage[(r + 8) * 130 + c + 1] = acc[i][j][3];
        }
    }
    __syncthreads();

    #pragma unroll
    for (int it = 0; it < 16; it++) {
        const int m = it * 8 + wid;
        const float bi = bias[m0 + m];
        float* crow = &C[(size_t)(m0 + m) * HW + n0];
        #pragma unroll
        for (int jj = 0; jj < 4; jj++) {
            int n = (tid & 31) + jj * 32;
            crow[n] = stage[m * 130 + n] + bi;
        }
    }
#undef ISSUE_SLAB
}

// ===========================================================================
// Window MHA (round-7 exact compute). SHIFT=0 -> g_attnT, SHIFT=4 -> g_attnT2.
// Merged into one launch: blockIdx.x < 256 selects branch 1.
// ===========================================================================
template <int SHIFT, int NW>
static __device__ __forceinline__ void wattn_body(
    int widx, float* q_sm, float* k_sm, float* v_sm)
{
    const int tid  = threadIdx.x;
    const int head = blockIdx.y;
    const int b    = blockIdx.z;
    const int wy = widx / NW, wx = widx % NW;
    const int y0 = wy * 8 - SHIFT, x0 = wx * 8 - SHIFT;

    const float* base = g_qkv + (size_t)b * C3 * HW;
    const int chq = head * HD;

    #pragma unroll
    for (int it = 0; it < 16; it++) {
        int idx = tid + it * 256;        // idx = d*64 + n
        int d = idx >> 6, n = idx & 63;
        int y = y0 + (n >> 3), x = x0 + (n & 7);
        float qv = 0.f, kv = 0.f, vv = 0.f;
        if (SHIFT == 0 || ((unsigned)y < H_ && (unsigned)x < W_)) {
            size_t poff = (size_t)y * W_ + x;
            qv = base[(size_t)(chq + d) * HW + poff];
            kv = base[(size_t)(CQ + chq + d) * HW + poff];
            vv = base[(size_t)(2 * CQ + chq + d) * HW + poff];
        }
        q_sm[idx] = qv;
        k_sm[idx] = kv;
        v_sm[n * 64 + (d ^ ((n & 15) << 2))] = vv;
    }
    __syncthreads();

    const int tc = tid & 15;
    const int tr = tid >> 4;
    const int r0 = tr * 4, c0 = tc * 4;

    float s[4][4];
    #pragma unroll
    for (int i = 0; i < 4; i++)
        #pragma unroll
        for (int j = 0; j < 4; j++) s[i][j] = 0.f;

    for (int d = 0; d < 64; d++) {
        float4 qv = *(const float4*)&q_sm[d * 64 + r0];
        float4 kv = *(const float4*)&k_sm[d * 64 + c0];
        float qa[4] = {qv.x, qv.y, qv.z, qv.w};
        float ka[4] = {kv.x, kv.y, kv.z, kv.w};
        #pragma unroll
        for (int i = 0; i < 4; i++)
            #pragma unroll
            for (int j = 0; j < 4; j++)
                s[i][j] += qa[i] * ka[j];
    }

    const float scale = 0.125f;
    float inv[4];
    #pragma unroll
    for (int i = 0; i < 4; i++) {
        float m = fmaxf(fmaxf(s[i][0], s[i][1]), fmaxf(s[i][2], s[i][3]));
        m = fmaxf(m, __shfl_xor_sync(0xffffffffu, m, 1));
        m = fmaxf(m, __shfl_xor_sync(0xffffffffu, m, 2));
        m = fmaxf(m, __shfl_xor_sync(0xffffffffu, m, 4));
        m = fmaxf(m, __shfl_xor_sync(0xffffffffu, m, 8));
        float sum = 0.f;
        #pragma unroll
        for (int j = 0; j < 4; j++) {
            s[i][j] = __expf((s[i][j] - m) * scale);
            sum += s[i][j];
        }
        sum += __shfl_xor_sync(0xffffffffu, sum, 1);
        sum += __shfl_xor_sync(0xffffffffu, sum, 2);
        sum += __shfl_xor_sync(0xffffffffu, sum, 4);
        sum += __shfl_xor_sync(0xffffffffu, sum, 8);
        inv[i] = 1.f / sum;
    }

    __syncthreads();

    #pragma unroll
    for (int i = 0; i < 4; i++) {
        float4 p4;
        p4.x = s[i][0] * inv[i]; p4.y = s[i][1] * inv[i];
        p4.z = s[i][2] * inv[i]; p4.w = s[i][3] * inv[i];
        *(float4*)&q_sm[(r0 + i) * 64 + c0] = p4;
    }
    __syncthreads();

    float o[4][4];
    #pragma unroll
    for (int i = 0; i < 4; i++)
        #pragma unroll
        for (int j = 0; j < 4; j++) o[i][j] = 0.f;

    for (int j0 = 0; j0 < 64; j0 += 4) {
        float4 p4[4];
        #pragma unroll
        for (int i = 0; i < 4; i++)
            p4[i] = *(const float4*)&q_sm[(r0 + i) * 64 + j0];
        #pragma unroll
        for (int jj = 0; jj < 4; jj++) {
            int j = j0 + jj;
            float4 vv = *(const float4*)&v_sm[j * 64 + (c0 ^ ((j & 15) << 2))];
            float pj[4] = {p4[0].x, p4[1].x, p4[2].x, p4[3].x};
            if (jj == 1) { pj[0]=p4[0].y; pj[1]=p4[1].y; pj[2]=p4[2].y; pj[3]=p4[3].y; }
            if (jj == 2) { pj[0]=p4[0].z; pj[1]=p4[1].z; pj[2]=p4[2].z; pj[3]=p4[3].z; }
            if (jj == 3) { pj[0]=p4[0].w; pj[1]=p4[1].w; pj[2]=p4[2].w; pj[3]=p4[3].w; }
            #pragma unroll
            for (int i = 0; i < 4; i++) {
                o[i][0] += pj[i] * vv.x; o[i][1] += pj[i] * vv.y;
                o[i][2] += pj[i] * vv.z; o[i][3] += pj[i] * vv.w;
            }
        }
    }

    float* outbuf = (SHIFT == 0) ? g_attnT : g_attnT2;
    #pragma unroll
    for (int i = 0; i < 4; i++) {
        int n = r0 + i;
        int y = y0 + (n >> 3), x = x0 + (n & 7);
        if (SHIFT == 0 || ((unsigned)y < H_ && (unsigned)x < W_)) {
            float* op = outbuf + ((size_t)b * HW + (size_t)y * W_ + x) * CQ
                      + chq + c0;
            float4 w4;
            w4.x = o[i][0]; w4.y = o[i][1]; w4.z = o[i][2]; w4.w = o[i][3];
            *(float4*)op = w4;
        }
    }
}

__global__ __launch_bounds__(256) void wattn_all_kernel()
{
    __shared__ float q_sm[64 * 64];
    __shared__ float k_sm[64 * 64];
    __shared__ float v_sm[64 * 64];
    if (blockIdx.x < 256)
        wattn_body<0, 16>(blockIdx.x, q_sm, k_sm, v_sm);
    else
        wattn_body<4, 17>(blockIdx.x - 256, q_sm, k_sm, v_sm);
}

// ---------------------------------------------------------------------------
extern "C" void kernel_launch(void* const* d_in, const int* in_sizes, int n_in,
                              void* d_out, int out_size)
{
    (void)in_sizes; (void)n_in; (void)out_size;
    const float* x      = (const float*)d_in[0];
    const float* w_qkv  = (const float*)d_in[1];
    const float* b_qkv  = (const float*)d_in[2];
    const float* w_head = (const float*)d_in[3];
    const float* b_head = (const float*)d_in[4];
    float* out = (float*)d_out;

    cudaFuncSetAttribute(gemm_bf16x3_kernel,
                         cudaFuncAttributeMaxDynamicSharedMemorySize, GEMM_SMEM);

    // 0a) split weights (device-side symbol selection)
    prep_w_kernel<<<(C3 * KDIM / 4 + 255) / 256, 256>>>(w_qkv, 0, C3 * KDIM / 4);
    prep_w_kernel<<<(CQ * KDIM / 4 + 255) / 256, 256>>>(w_head, 1, CQ * KDIM / 4);
    // 0b) transpose + split x -> g_xb_hi/lo [b][hw][c]
    {
        dim3 grid(HW / 32, CIN / 32, NB);
        transpose_x_kernel<<<grid, 256>>>(x);
    }
    // 1) qkv = w_qkv @ x + b_qkv  (M=1152)
    {
        dim3 grid(C3 / 128, HW / 128, NB);
        gemm_bf16x3_kernel<<<grid, 256, GEMM_SMEM>>>(b_qkv, nullptr, 0);
    }
    // 2+3) both window-attention branches, one launch
    {
        dim3 grid(256 + 289, NH, NB);
        wattn_all_kernel<<<grid, 256>>>();
    }
    // 3b) sum branches + split to bf16 hi/lo
    sum_split_kernel<<<(int)((size_t)NB * HW * CQ / 4 / 256), 256>>>();
    // 4) out = w_head @ (x1+x2) + b_head  (M=384)
    {
        dim3 grid(CQ / 128, HW / 128, NB);
        gemm_bf16x3_kernel<<<grid, 256, GEMM_SMEM>>>(b_head, out, 1);
    }
}

// round 14
// speedup vs baseline: 1.9597x; 1.1096x over previous
#include <cuda_runtime.h>
#include <cstdint>

#define H_ 128
#define W_ 128
#define HW 16384
#define CIN 384
#define CQ 384
#define C3 1152
#define NH 6
#define HD 64
#define NB 4
#define KDIM 384          // K for both GEMMs
#define NSLAB 12          // 384 / 32

// Scratch (no allocation allowed). RULE: device globals are referenced ONLY
// from device code — never passed as kernel args from host (ATS makes the
// host shadow symbol silently writable -> zero-filled device arrays).
__device__ float    g_qkv   [(size_t)NB * C3 * HW];   // qkv [b][c3][hw]
__device__ float    g_attnT [(size_t)NB * HW * CQ];   // branch-1 out (fp32)
__device__ float    g_attnT2[(size_t)NB * HW * CQ];   // branch-2 out (fp32)
__device__ uint16_t g_xb_hi [(size_t)NB * HW * CIN];  // x^T bf16 hi [b][hw][c]
__device__ uint16_t g_xb_lo [(size_t)NB * HW * CIN];
__device__ uint16_t g_at_hi [(size_t)NB * HW * CQ];   // (attn1+attn2) bf16 hi
__device__ uint16_t g_at_lo [(size_t)NB * HW * CQ];
__device__ uint16_t g_wq_hi [C3 * KDIM];
__device__ uint16_t g_wq_lo [C3 * KDIM];
__device__ uint16_t g_wh_hi [CQ * KDIM];
__device__ uint16_t g_wh_lo [CQ * KDIM];

// ===========================================================================
// helpers (baseline PTX, valid in every sm_103 gencode pass)
// ===========================================================================
static __device__ __forceinline__ void mma_bf16(
    float* d, const uint32_t* a, const uint32_t* b)
{
    asm volatile(
        "mma.sync.aligned.m16n8k16.row.col.f32.bf16.bf16.f32 "
        "{%0,%1,%2,%3}, {%4,%5,%6,%7}, {%8,%9}, {%0,%1,%2,%3};"
        : "+f"(d[0]), "+f"(d[1]), "+f"(d[2]), "+f"(d[3])
        : "r"(a[0]), "r"(a[1]), "r"(a[2]), "r"(a[3]),
          "r"(b[0]), "r"(b[1]));
}

static __device__ __forceinline__ void ldm4(uint32_t* r, uint32_t addr)
{
    asm volatile(
        "ldmatrix.sync.aligned.m8n8.x4.shared.b16 {%0,%1,%2,%3}, [%4];"
        : "=r"(r[0]), "=r"(r[1]), "=r"(r[2]), "=r"(r[3])
        : "r"(addr));
}

static __device__ __forceinline__ uint32_t smem_u32(const void* p) {
    uint32_t a;
    asm("{ .reg .u64 t; cvta.to.shared.u64 t, %1; cvt.u32.u64 %0, t; }"
        : "=r"(a) : "l"(p));
    return a;
}

static __device__ __forceinline__ uint32_t pack_bf16x2(float lo, float hi) {
    uint32_t r;
    asm("cvt.rn.bf16x2.f32 %0, %1, %2;" : "=r"(r) : "f"(hi), "f"(lo));
    return r;
}
static __device__ __forceinline__ float bf16lo_f(uint32_t r) {
    return __uint_as_float(r << 16);
}
static __device__ __forceinline__ float bf16hi_f(uint32_t r) {
    return __uint_as_float(r & 0xFFFF0000u);
}

// split 8 consecutive floats into bf16 hi/lo uint4s
static __device__ __forceinline__ void split8(const float* f, uint4& hi, uint4& lo)
{
    hi.x = pack_bf16x2(f[0], f[1]);
    hi.y = pack_bf16x2(f[2], f[3]);
    hi.z = pack_bf16x2(f[4], f[5]);
    hi.w = pack_bf16x2(f[6], f[7]);
    lo.x = pack_bf16x2(f[0] - bf16lo_f(hi.x), f[1] - bf16hi_f(hi.x));
    lo.y = pack_bf16x2(f[2] - bf16lo_f(hi.y), f[3] - bf16hi_f(hi.y));
    lo.z = pack_bf16x2(f[4] - bf16lo_f(hi.z), f[5] - bf16hi_f(hi.z));
    lo.w = pack_bf16x2(f[6] - bf16lo_f(hi.w), f[7] - bf16hi_f(hi.w));
}

#define CP_ASYNC16(sa, gp) \
    asm volatile("cp.async.cg.shared.global [%0], [%1], 16;" :: "r"(sa), "l"(gp))
#define CP_COMMIT() asm volatile("cp.async.commit_group;" ::: "memory")
#define CP_WAIT(n)  asm volatile("cp.async.wait_group %0;" :: "n"(n) : "memory")

// ===========================================================================
// prep: split weights into bf16 hi/lo (device-side target selection)
// ===========================================================================
__global__ __launch_bounds__(256) void prep_w_kernel(
    const float* __restrict__ w, int which, int n4)
{
    uint16_t* hi = which ? g_wh_hi : g_wq_hi;
    uint16_t* lo = which ? g_wh_lo : g_wq_lo;
    int i = blockIdx.x * 256 + threadIdx.x;
    if (i >= n4) return;
    float4 v = ((const float4*)w)[i];
    uint2 h, l;
    h.x = pack_bf16x2(v.x, v.y);
    h.y = pack_bf16x2(v.z, v.w);
    l.x = pack_bf16x2(v.x - bf16lo_f(h.x), v.y - bf16hi_f(h.x));
    l.y = pack_bf16x2(v.z - bf16lo_f(h.y), v.w - bf16hi_f(h.y));
    ((uint2*)hi)[i] = h;
    ((uint2*)lo)[i] = l;
}

// ===========================================================================
// Transpose + split: x[b][C][HW] -> g_xb_hi/lo [b][hw][c]
// ===========================================================================
__global__ __launch_bounds__(256) void transpose_x_kernel(const float* __restrict__ x)
{
    __shared__ float sm[32][33];
    const int z = blockIdx.z;
    const int hw0 = blockIdx.x * 32, c0 = blockIdx.y * 32;
    const float* xz = x + (size_t)z * CIN * HW;
    uint16_t* th = g_xb_hi + (size_t)z * HW * CIN;
    uint16_t* tl = g_xb_lo + (size_t)z * HW * CIN;
    const int t = threadIdx.x;
    const int tx = t & 31, ty = t >> 5;

    #pragma unroll
    for (int i = 0; i < 4; i++)
        sm[ty + 8 * i][tx] = xz[(size_t)(c0 + ty + 8 * i) * HW + hw0 + tx];
    __syncthreads();

    {
        int h = t >> 3, cp = (t & 7) * 4;
        float v0 = sm[cp + 0][h], v1 = sm[cp + 1][h];
        float v2 = sm[cp + 2][h], v3 = sm[cp + 3][h];
        uint2 hi, lo;
        hi.x = pack_bf16x2(v0, v1);
        hi.y = pack_bf16x2(v2, v3);
        lo.x = pack_bf16x2(v0 - bf16lo_f(hi.x), v1 - bf16hi_f(hi.x));
        lo.y = pack_bf16x2(v2 - bf16lo_f(hi.y), v3 - bf16hi_f(hi.y));
        size_t off = (size_t)(hw0 + h) * CIN + c0 + cp;
        *(uint2*)&th[off] = hi;
        *(uint2*)&tl[off] = lo;
    }
}

// ===========================================================================
// sum + split: g_at_hi/lo = split(g_attnT + g_attnT2)
// ===========================================================================
__global__ __launch_bounds__(256) void sum_split_kernel()
{
    int i = blockIdx.x * 256 + threadIdx.x;   // float4 index
    float4 a = ((const float4*)g_attnT)[i];
    float4 b = ((const float4*)g_attnT2)[i];
    float v0 = a.x + b.x, v1 = a.y + b.y, v2 = a.z + b.z, v3 = a.w + b.w;
    uint2 h, l;
    h.x = pack_bf16x2(v0, v1);
    h.y = pack_bf16x2(v2, v3);
    l.x = pack_bf16x2(v0 - bf16lo_f(h.x), v1 - bf16hi_f(h.x));
    l.y = pack_bf16x2(v2 - bf16lo_f(h.y), v3 - bf16hi_f(h.y));
    ((uint2*)g_at_hi)[i] = h;
    ((uint2*)g_at_lo)[i] = l;
}

// ===========================================================================
// bf16x3-split tensor-core GEMM (round-13 exact).
// ===========================================================================
#define RSB   64
#define ABUF  8192
#define SMBUF 32768
#define NSTG  3
#define GEMM_SMEM (NSTG * SMBUF)

__global__ __launch_bounds__(256, 2) void gemm_bf16x3_kernel(
    const float* __restrict__ bias, float* __restrict__ Cext, int mode)
{
    extern __shared__ char dynsm[];
    const uint32_t sbase = smem_u32(dynsm);

    const int tid  = threadIdx.x;
    const int lane = tid & 31;
    const int wid  = tid >> 5;
    const int m0 = blockIdx.x * 128;
    const int n0 = blockIdx.y * 128;
    const int z  = blockIdx.z;

    const uint16_t* Ahi = (mode == 0) ? g_wq_hi : g_wh_hi;
    const uint16_t* Alo = (mode == 0) ? g_wq_lo : g_wh_lo;
    const uint16_t* Bhi = ((mode == 0) ? g_xb_hi : g_at_hi) + (size_t)z * HW * KDIM;
    const uint16_t* Blo = ((mode == 0) ? g_xb_lo : g_at_lo) + (size_t)z * HW * KDIM;
    float* C = (mode == 0) ? (g_qkv + (size_t)z * C3 * HW)
                           : (Cext  + (size_t)z * CQ * HW);

    const uint16_t* gptr[8];
    uint32_t soff[8];
    #pragma unroll
    for (int i = 0; i < 8; i++) {
        int id  = i * 256 + tid;
        int arr = id >> 9;
        int idx = id & 511;
        int r   = idx >> 2;
        int q   = idx & 3;
        const uint16_t* base =
            (arr == 0) ? Ahi + (size_t)(m0 + r) * KDIM :
            (arr == 1) ? Alo + (size_t)(m0 + r) * KDIM :
            (arr == 2) ? Bhi + (size_t)(n0 + r) * KDIM :
                         Blo + (size_t)(n0 + r) * KDIM;
        gptr[i] = base + q * 8;
        soff[i] = (uint32_t)(arr * ABUF + r * RSB + ((q ^ ((r >> 1) & 3)) * 16));
    }

#define ISSUE_SLAB(k0, bufOff) do {                                           \
        _Pragma("unroll")                                                     \
        for (int i = 0; i < 8; i++)                                           \
            CP_ASYNC16(sbase + (bufOff) + soff[i], gptr[i] + (k0));           \
        CP_COMMIT();                                                          \
    } while (0)

    const int mbase = (wid & 3) * 32;
    const int nbase = (wid >> 2) * 64;
    const int row_a = (lane & 7) + ((lane >> 3) & 1) * 8;
    const int qa_hi = lane >> 4;
    const int row_b = (lane & 7) + (lane >> 4) * 8;
    const int qb_hi = (lane >> 3) & 1;

    float acc[2][8][4];
    #pragma unroll
    for (int i = 0; i < 2; i++)
        #pragma unroll
        for (int j = 0; j < 8; j++)
            #pragma unroll
            for (int r = 0; r < 4; r++) acc[i][j][r] = 0.f;

    ISSUE_SLAB(0, 0);
    ISSUE_SLAB(32, SMBUF);

    for (int s = 0; s < NSLAB; s++) {
        if (s + 1 < NSLAB) CP_WAIT(1);
        else               CP_WAIT(0);
        __syncthreads();
        if (s + 2 < NSLAB) ISSUE_SLAB((s + 2) * 32, ((s + 2) % NSTG) * SMBUF);

        const uint32_t base = sbase + (s % NSTG) * SMBUF;
        #pragma unroll
        for (int kc = 0; kc < 2; kc++) {
            uint32_t af[2][4], al[2][4], bf[4][4];
            #pragma unroll
            for (int i = 0; i < 2; i++) {
                int rw = mbase + i * 16 + row_a;
                uint32_t c = (uint32_t)((2 * kc + qa_hi) ^ ((rw >> 1) & 3));
                uint32_t ra_ = base + rw * RSB + c * 16;
                ldm4(af[i], ra_);
                ldm4(al[i], ra_ + ABUF);
            }
            #pragma unroll
            for (int p = 0; p < 4; p++) {
                int rw = nbase + p * 16 + row_b;
                uint32_t c = (uint32_t)((2 * kc + qb_hi) ^ ((rw >> 1) & 3));
                ldm4(bf[p], base + 2 * ABUF + rw * RSB + c * 16);
            }
            #pragma unroll
            for (int i = 0; i < 2; i++)
                #pragma unroll
                for (int j = 0; j < 8; j++)
                    mma_bf16(acc[i][j], af[i], &bf[j >> 1][(j & 1) * 2]);
            #pragma unroll
            for (int i = 0; i < 2; i++)
                #pragma unroll
                for (int j = 0; j < 8; j++)
                    mma_bf16(acc[i][j], al[i], &bf[j >> 1][(j & 1) * 2]);
            #pragma unroll
            for (int p = 0; p < 4; p++) {
                int rw = nbase + p * 16 + row_b;
                uint32_t c = (uint32_t)((2 * kc + qb_hi) ^ ((rw >> 1) & 3));
                ldm4(bf[p], base + 3 * ABUF + rw * RSB + c * 16);
            }
            #pragma unroll
            for (int i = 0; i < 2; i++)
                #pragma unroll
                for (int j = 0; j < 8; j++)
                    mma_bf16(acc[i][j], af[i], &bf[j >> 1][(j & 1) * 2]);
        }
    }
    __syncthreads();

    float* stage = (float*)dynsm;   // [128][130]
    #pragma unroll
    for (int i = 0; i < 2; i++) {
        #pragma unroll
        for (int j = 0; j < 8; j++) {
            int r = mbase + i * 16 + (lane >> 2);
            int c = nbase + j * 8 + (lane & 3) * 2;
            stage[r * 130 + c]           = acc[i][j][0];
            stage[r * 130 + c + 1]       = acc[i][j][1];
            stage[(r + 8) * 130 + c]     = acc[i][j][2];
            stage[(r + 8) * 130 + c + 1] = acc[i][j][3];
        }
    }
    __syncthreads();

    #pragma unroll
    for (int it = 0; it < 16; it++) {
        const int m = it * 8 + wid;
        const float bi = bias[m0 + m];
        float* crow = &C[(size_t)(m0 + m) * HW + n0];
        #pragma unroll
        for (int jj = 0; jj < 4; jj++) {
            int n = (tid & 31) + jj * 32;
            crow[n] = stage[m * 130 + n] + bi;
        }
    }
#undef ISSUE_SLAB
}

// ===========================================================================
// Window MHA v4: tensor-core (mma.sync bf16, hi/lo split on Q,K,P,V).
// Per block: (window, head). 8 warps: warp w -> query m16-tile (w&3),
// output d-half (w>>2); each warp computes its FULL S rows (duplicated
// across d-halves) so softmax is warp-local.
// smem: fp32 staging Q[64][65], K[64][65], V[64][64] then 6 bf16 arrays
// [64][64] with 16B-chunk swizzle pos = chunk ^ (row&7).
// ===========================================================================
#define AT_STGQ 0
#define AT_STGK 16640
#define AT_STGV 33280
#define AT_QH   49664
#define AT_SMEM (49664 + 6 * 8192)   // 98816

template <int SHIFT, int NW>
static __device__ __forceinline__ void wattn_body(int widx, char* sm)
{
    const int tid  = threadIdx.x;
    const int lane = tid & 31;
    const int w    = tid >> 5;
    const int head = blockIdx.y;
    const int b    = blockIdx.z;
    const int wy = widx / NW, wx = widx % NW;
    const int y0 = wy * 8 - SHIFT, x0 = wx * 8 - SHIFT;

    const float* base = g_qkv + (size_t)b * C3 * HW;
    const int chq = head * HD;

    float* stgQ = (float*)(sm + AT_STGQ);   // [64][65]
    float* stgK = (float*)(sm + AT_STGK);   // [64][65]
    float* stgV = (float*)(sm + AT_STGV);   // [64][64]
    char* qh = sm + AT_QH;
    char* ql = qh + 8192;
    char* kh = qh + 16384;
    char* kl = qh + 24576;
    char* vh = qh + 32768;
    char* vl = qh + 40960;

    // ---- phase 1: fp32 load into staging ----
    #pragma unroll
    for (int it = 0; it < 16; it++) {
        int idx = tid + it * 256;        // idx = d*64 + n
        int d = idx >> 6, n = idx & 63;
        int y = y0 + (n >> 3), x = x0 + (n & 7);
        float qv = 0.f, kv = 0.f, vv = 0.f;
        if (SHIFT == 0 || ((unsigned)y < H_ && (unsigned)x < W_)) {
            size_t poff = (size_t)y * W_ + x;
            qv = base[(size_t)(chq + d) * HW + poff];
            kv = base[(size_t)(CQ + chq + d) * HW + poff];
            vv = base[(size_t)(2 * CQ + chq + d) * HW + poff];
        }
        stgQ[d * 65 + n] = qv;
        stgK[d * 65 + n] = kv;
        stgV[d * 64 + n] = vv;
    }
    __syncthreads();

    // ---- phase 2a: Q,K transpose-convert -> [n][d] bf16 hi/lo, swizzled ----
    #pragma unroll
    for (int a2 = 0; a2 < 2; a2++) {
        int id = a2 * 256 + tid;         // 0..511
        int n = id >> 3, c = id & 7;
        uint32_t dst = (uint32_t)(n * 128 + ((c ^ (n & 7)) * 16));
        float f[8];
        #pragma unroll
        for (int i = 0; i < 8; i++) f[i] = stgQ[(c * 8 + i) * 65 + n];
        uint4 hi, lo;
        split8(f, hi, lo);
        *(uint4*)(qh + dst) = hi;
        *(uint4*)(ql + dst) = lo;
        #pragma unroll
        for (int i = 0; i < 8; i++) f[i] = stgK[(c * 8 + i) * 65 + n];
        split8(f, hi, lo);
        *(uint4*)(kh + dst) = hi;
        *(uint4*)(kl + dst) = lo;
    }
    // ---- phase 2b: V convert -> [d][j] bf16 hi/lo, swizzled (no transpose) --
    #pragma unroll
    for (int v2 = 0; v2 < 2; v2++) {
        int id = v2 * 256 + tid;
        int d = id >> 3, c = id & 7;
        float f[8];
        *(float4*)&f[0] = *(const float4*)&stgV[d * 64 + c * 8];
        *(float4*)&f[4] = *(const float4*)&stgV[d * 64 + c * 8 + 4];
        uint4 hi, lo;
        split8(f, hi, lo);
        uint32_t dst = (uint32_t)(d * 128 + ((c ^ (d & 7)) * 16));
        *(uint4*)(vh + dst) = hi;
        *(uint4*)(vl + dst) = lo;
    }
    __syncthreads();

    // ---- per-warp tiles ----
    const int mt = w & 3;                // query 16-row tile
    const int dh = w >> 2;               // output d-half (0/1)
    const int row_a = (lane & 7) + ((lane >> 3) & 1) * 8;
    const int qa_hi = lane >> 4;
    const int row_b = (lane & 7) + (lane >> 4) * 8;
    const int qb_hi = (lane >> 3) & 1;

    const uint32_t qh_a = smem_u32(qh);
    const uint32_t kh_a = smem_u32(kh);
    const uint32_t vh_a = smem_u32(vh);

    // ---- phase 3: S = Q K^T (bf16x3) ----
    float acc[8][4];
    #pragma unroll
    for (int j = 0; j < 8; j++)
        #pragma unroll
        for (int r = 0; r < 4; r++) acc[j][r] = 0.f;

    #pragma unroll
    for (int kc = 0; kc < 4; kc++) {
        uint32_t aq[4], aql[4], bh[4][4], bl[4][4];
        {
            int rw = mt * 16 + row_a;
            uint32_t cc = (uint32_t)((2 * kc + qa_hi) ^ (rw & 7));
            uint32_t ra = qh_a + rw * 128 + cc * 16;
            ldm4(aq, ra);
            ldm4(aql, ra + 8192);
        }
        #pragma unroll
        for (int p = 0; p < 4; p++) {
            int rw = p * 16 + row_b;
            uint32_t cc = (uint32_t)((2 * kc + qb_hi) ^ (rw & 7));
            uint32_t rb = kh_a + rw * 128 + cc * 16;
            ldm4(bh[p], rb);
            ldm4(bl[p], rb + 8192);
        }
        #pragma unroll
        for (int j = 0; j < 8; j++)
            mma_bf16(acc[j], aq, &bh[j >> 1][(j & 1) * 2]);
        #pragma unroll
        for (int j = 0; j < 8; j++)
            mma_bf16(acc[j], aql, &bh[j >> 1][(j & 1) * 2]);
        #pragma unroll
        for (int j = 0; j < 8; j++)
            mma_bf16(acc[j], aq, &bl[j >> 1][(j & 1) * 2]);
    }

    // ---- phase 4: softmax (warp-local; rows r=lane>>2 and r+8) ----
    const float scale = 0.125f;
    float mx0 = acc[0][0], mx1 = acc[0][2];
    #pragma unroll
    for (int j = 0; j < 8; j++) {
        mx0 = fmaxf(mx0, fmaxf(acc[j][0], acc[j][1]));
        mx1 = fmaxf(mx1, fmaxf(acc[j][2], acc[j][3]));
    }
    mx0 = fmaxf(mx0, __shfl_xor_sync(0xffffffffu, mx0, 1));
    mx0 = fmaxf(mx0, __shfl_xor_sync(0xffffffffu, mx0, 2));
    mx1 = fmaxf(mx1, __shfl_xor_sync(0xffffffffu, mx1, 1));
    mx1 = fmaxf(mx1, __shfl_xor_sync(0xffffffffu, mx1, 2));
    float sum0 = 0.f, sum1 = 0.f;
    #pragma unroll
    for (int j = 0; j < 8; j++) {
        acc[j][0] = __expf((acc[j][0] - mx0) * scale); sum0 += acc[j][0];
        acc[j][1] = __expf((acc[j][1] - mx0) * scale); sum0 += acc[j][1];
        acc[j][2] = __expf((acc[j][2] - mx1) * scale); sum1 += acc[j][2];
        acc[j][3] = __expf((acc[j][3] - mx1) * scale); sum1 += acc[j][3];
    }
    sum0 += __shfl_xor_sync(0xffffffffu, sum0, 1);
    sum0 += __shfl_xor_sync(0xffffffffu, sum0, 2);
    sum1 += __shfl_xor_sync(0xffffffffu, sum1, 1);
    sum1 += __shfl_xor_sync(0xffffffffu, sum1, 2);
    const float inv0 = 1.f / sum0, inv1 = 1.f / sum1;

    // ---- repack P into A-frags (hi/lo) ----
    uint32_t aph[4][4], apl[4][4];
    #pragma unroll
    for (int kc = 0; kc < 4; kc++) {
        const int j0 = 2 * kc, j1 = 2 * kc + 1;
        float p00 = acc[j0][0] * inv0, p01 = acc[j0][1] * inv0;
        float p02 = acc[j0][2] * inv1, p03 = acc[j0][3] * inv1;
        float p10 = acc[j1][0] * inv0, p11 = acc[j1][1] * inv0;
        float p12 = acc[j1][2] * inv1, p13 = acc[j1][3] * inv1;
        uint32_t h;
        h = pack_bf16x2(p00, p01); aph[kc][0] = h;
        apl[kc][0] = pack_bf16x2(p00 - bf16lo_f(h), p01 - bf16hi_f(h));
        h = pack_bf16x2(p02, p03); aph[kc][1] = h;
        apl[kc][1] = pack_bf16x2(p02 - bf16lo_f(h), p03 - bf16hi_f(h));
        h = pack_bf16x2(p10, p11); aph[kc][2] = h;
        apl[kc][2] = pack_bf16x2(p10 - bf16lo_f(h), p11 - bf16hi_f(h));
        h = pack_bf16x2(p12, p13); aph[kc][3] = h;
        apl[kc][3] = pack_bf16x2(p12 - bf16lo_f(h), p13 - bf16hi_f(h));
    }

    // ---- phase 5: O = P V (bf16x3), d-half per warp ----
    float oacc[4][4];
    #pragma unroll
    for (int t = 0; t < 4; t++)
        #pragma unroll
        for (int r = 0; r < 4; r++) oacc[t][r] = 0.f;

    #pragma unroll
    for (int kc = 0; kc < 4; kc++) {
        uint32_t bvh[2][4], bvl[2][4];
        #pragma unroll
        for (int p = 0; p < 2; p++) {
            int rw = dh * 32 + p * 16 + row_b;
            uint32_t cc = (uint32_t)((2 * kc + qb_hi) ^ (rw & 7));
            uint32_t rb = vh_a + rw * 128 + cc * 16;
            ldm4(bvh[p], rb);
            ldm4(bvl[p], rb + 8192);
        }
        #pragma unroll
        for (int t = 0; t < 4; t++)
            mma_bf16(oacc[t], aph[kc], &bvh[t >> 1][(t & 1) * 2]);
        #pragma unroll
        for (int t = 0; t < 4; t++)
            mma_bf16(oacc[t], apl[kc], &bvh[t >> 1][(t & 1) * 2]);
        #pragma unroll
        for (int t = 0; t < 4; t++)
            mma_bf16(oacc[t], aph[kc], &bvl[t >> 1][(t & 1) * 2]);
    }

    // ---- phase 6: store O ----
    float* outbuf = (SHIFT == 0) ? g_attnT : g_attnT2;
    const int ntok0 = mt * 16 + (lane >> 2);
    const int cb = chq + dh * 32 + (lane & 3) * 2;
    #pragma unroll
    for (int half = 0; half < 2; half++) {
        int n = ntok0 + half * 8;
        int y = y0 + (n >> 3), x = x0 + (n & 7);
        if (SHIFT == 0 || ((unsigned)y < H_ && (unsigned)x < W_)) {
            float* op = outbuf + ((size_t)b * HW + (size_t)y * W_ + x) * CQ;
            #pragma unroll
            for (int t = 0; t < 4; t++) {
                float2 v;
                v.x = oacc[t][half * 2 + 0];
                v.y = oacc[t][half * 2 + 1];
                *(float2*)&op[cb + t * 8] = v;
            }
        }
    }
}

__global__ __launch_bounds__(256) void wattn_all_kernel()
{
    extern __shared__ char dynat[];
    if (blockIdx.x < 256)
        wattn_body<0, 16>(blockIdx.x, dynat);
    else
        wattn_body<4, 17>(blockIdx.x - 256, dynat);
}

// ---------------------------------------------------------------------------
extern "C" void kernel_launch(void* const* d_in, const int* in_sizes, int n_in,
                              void* d_out, int out_size)
{
    (void)in_sizes; (void)n_in; (void)out_size;
    const float* x      = (const float*)d_in[0];
    const float* w_qkv  = (const float*)d_in[1];
    const float* b_qkv  = (const float*)d_in[2];
    const float* w_head = (const float*)d_in[3];
    const float* b_head = (const float*)d_in[4];
    float* out = (float*)d_out;

    cudaFuncSetAttribute(gemm_bf16x3_kernel,
                         cudaFuncAttributeMaxDynamicSharedMemorySize, GEMM_SMEM);
    cudaFuncSetAttribute(wattn_all_kernel,
                         cudaFuncAttributeMaxDynamicSharedMemorySize, AT_SMEM);

    // 0a) split weights (device-side symbol selection)
    prep_w_kernel<<<(C3 * KDIM / 4 + 255) / 256, 256>>>(w_qkv, 0, C3 * KDIM / 4);
    prep_w_kernel<<<(CQ * KDIM / 4 + 255) / 256, 256>>>(w_head, 1, CQ * KDIM / 4);
    // 0b) transpose + split x -> g_xb_hi/lo [b][hw][c]
    {
        dim3 grid(HW / 32, CIN / 32, NB);
        transpose_x_kernel<<<grid, 256>>>(x);
    }
    // 1) qkv = w_qkv @ x + b_qkv  (M=1152)
    {
        dim3 grid(C3 / 128, HW / 128, NB);
        gemm_bf16x3_kernel<<<grid, 256, GEMM_SMEM>>>(b_qkv, nullptr, 0);
    }
    // 2+3) both window-attention branches, one launch (tensor-core)
    {
        dim3 grid(256 + 289, NH, NB);
        wattn_all_kernel<<<grid, 256, AT_SMEM>>>();
    }
    // 3b) sum branches + split to bf16 hi/lo
    sum_split_kernel<<<(int)((size_t)NB * HW * CQ / 4 / 256), 256>>>();
    // 4) out = w_head @ (x1+x2) + b_head  (M=384)
    {
        dim3 grid(CQ / 128, HW / 128, NB);
        gemm_bf16x3_kernel<<<grid, 256, GEMM_SMEM>>>(b_head, out, 1);
    }
}